// round 10
// baseline (speedup 1.0000x reference)
#include <cuda_runtime.h>
#include <cuda_bf16.h>
#include <cstdint>
#include <math.h>

#define NTOK 384
#define CDIM 128
#define NROWS (NTOK*NTOK)   /* 147456 */
#define EPSV 1e-5f

// Scratch (no cudaMalloc allowed)
__device__ float g_gate[(size_t)NROWS*CDIM];
__device__ float g_tri [(size_t)NROWS*CDIM];           // [c][i*384+j]
__device__ __nv_bfloat16 g_Lhi[(size_t)CDIM*NROWS];    // [c][i*384+k]
__device__ __nv_bfloat16 g_Llo[(size_t)CDIM*NROWS];
__device__ __nv_bfloat16 g_Rhi[(size_t)CDIM*NROWS];    // [c][j*384+k]
__device__ __nv_bfloat16 g_Rlo[(size_t)CDIM*NROWS];

// fast sigmoid: MUFU.EX2 + MUFU.RCP path (rel err ~2^-21, tolerance is 1e-3)
__device__ __forceinline__ float fsig(float z){
  return __fdividef(1.f, 1.f + __expf(-z));
}

__device__ __forceinline__ uint32_t tf32_rna(float f){
  uint32_t r; asm("cvt.rna.tf32.f32 %0, %1;" : "=r"(r) : "f"(f)); return r;
}
__device__ __forceinline__ uint32_t prmt_(uint32_t a, uint32_t b, uint32_t s){
  uint32_t d; asm("prmt.b32 %0,%1,%2,%3;" : "=r"(d) : "r"(a), "r"(b), "r"(s)); return d;
}
__device__ __forceinline__ uint32_t pack_hilo(float v){
  __nv_bfloat16 h = __float2bfloat16(v);
  float rem = v - __bfloat162float(h);
  __nv_bfloat16 l = __float2bfloat16(rem);
  uint16_t hb = *reinterpret_cast<uint16_t*>(&h);
  uint16_t lb = *reinterpret_cast<uint16_t*>(&l);
  return (uint32_t)hb | ((uint32_t)lb << 16);
}
__device__ __forceinline__ uint32_t smem_u32(const void* p){
  uint32_t a;
  asm("{ .reg .u64 t; cvta.to.shared.u64 t, %1; cvt.u32.u64 %0, t; }" : "=r"(a) : "l"(p));
  return a;
}
__device__ __forceinline__ void cp16(uint32_t dst_smem, const void* src){
  asm volatile("cp.async.ca.shared.global [%0], [%1], 16;" :: "r"(dst_smem), "l"(src));
}
__device__ __forceinline__ void cp_commit(){
  asm volatile("cp.async.commit_group;");
}
template<int N>
__device__ __forceinline__ void cp_wait(){
  asm volatile("cp.async.wait_group %0;" :: "n"(N));
}

// m16n8k8 tf32 mma (sm_80 base ISA)
__device__ __forceinline__ void mma_tf32(float& d0, float& d1, float& d2, float& d3,
                                         uint32_t a0, uint32_t a1, uint32_t a2, uint32_t a3,
                                         uint32_t b0, uint32_t b1){
  asm volatile(
    "mma.sync.aligned.m16n8k8.row.col.f32.tf32.tf32.f32 "
    "{%0,%1,%2,%3}, {%4,%5,%6,%7}, {%8,%9}, {%0,%1,%2,%3};"
    : "+f"(d0), "+f"(d1), "+f"(d2), "+f"(d3)
    : "r"(a0), "r"(a1), "r"(a2), "r"(a3), "r"(b0), "r"(b1));
}

// m16n8k16 bf16 mma (sm_80 base ISA)
__device__ __forceinline__ void mma_bf16(float* d, const uint32_t* a, uint32_t b0, uint32_t b1){
  asm volatile(
    "mma.sync.aligned.m16n8k16.row.col.f32.bf16.bf16.f32 "
    "{%0,%1,%2,%3}, {%4,%5,%6,%7}, {%8,%9}, {%0,%1,%2,%3};"
    : "+f"(d[0]), "+f"(d[1]), "+f"(d[2]), "+f"(d[3])
    : "r"(a[0]), "r"(a[1]), "r"(a[2]), "r"(a[3]), "r"(b0), "r"(b1));
}

// ================= fused LN + 5 projections =================
#define LDX 132
#define LDW 136
#define LDE 132
#define XS_WORDS (128*LDX)
#define W_WORDS  (128*LDW)
#define PROJALL_SMEM ((XS_WORDS + 2*W_WORDS)*4)

// GEMM-pair mainloop: acc1 += xs@w1, (dual) acc2 += xs@w2
__device__ __forceinline__ void gemm_pair(const uint32_t* __restrict__ xs,
                                          const uint32_t* __restrict__ w1,
                                          const uint32_t* __restrict__ w2,
                                          int wm, int wn, int gid, int tig,
                                          float acc1[2][4][4], float acc2[2][4][4],
                                          bool dual){
  const uint32_t* xa  = xs + (wm*32 + gid)*LDX + tig;
  const uint32_t* wb1 = w1 + tig*LDW + wn*32 + gid;
  const uint32_t* wb2 = w2 + tig*LDW + wn*32 + gid;
  #pragma unroll
  for (int kc=0; kc<16; kc++){
    uint32_t a[2][4];
    #pragma unroll
    for (int t=0;t<2;t++){
      const uint32_t* p = xa + t*16*LDX + kc*8;
      a[t][0] = p[0];
      a[t][1] = p[8*LDX];
      a[t][2] = p[4];
      a[t][3] = p[8*LDX + 4];
    }
    #pragma unroll
    for (int u=0;u<4;u++){
      const uint32_t* q1 = wb1 + kc*8*LDW + u*8;
      uint32_t b10 = q1[0], b11 = q1[4*LDW];
      #pragma unroll
      for (int t=0;t<2;t++)
        mma_tf32(acc1[t][u][0],acc1[t][u][1],acc1[t][u][2],acc1[t][u][3],
                 a[t][0],a[t][1],a[t][2],a[t][3], b10,b11);
      if (dual){
        const uint32_t* q2 = wb2 + kc*8*LDW + u*8;
        uint32_t b20 = q2[0], b21 = q2[4*LDW];
        #pragma unroll
        for (int t=0;t<2;t++)
          mma_tf32(acc2[t][u][0],acc2[t][u][1],acc2[t][u][2],acc2[t][u][3],
                   a[t][0],a[t][1],a[t][2],a[t][3], b20,b21);
      }
    }
  }
}

// LDG one 128x128 W into registers (raw fp32 bits)
__device__ __forceinline__ void ldgW(const float* __restrict__ W, int tid, uint4 w[8]){
  #pragma unroll
  for (int it=0; it<8; ++it){
    int slot = tid + it*512;
    int r  = slot >> 5;
    int kv = slot & 31;
    w[it] = *reinterpret_cast<const uint4*>(&W[r*CDIM + kv*4]);
  }
}
// cvt tf32 + STS into a W smem buffer
__device__ __forceinline__ void stsW(const uint4 w[8], int tid, uint32_t* __restrict__ dst){
  #pragma unroll
  for (int it=0; it<8; ++it){
    int slot = tid + it*512;
    int r  = slot >> 5;
    int kv = slot & 31;
    float4 v = *reinterpret_cast<const float4*>(&w[it]);
    uint4 t; t.x=tf32_rna(v.x); t.y=tf32_rna(v.y); t.z=tf32_rna(v.z); t.w=tf32_rna(v.w);
    *reinterpret_cast<uint4*>(&dst[r*LDW + kv*4]) = t;
  }
}

// bias+sigmoid+mask -> (hi,lo) packed words
__device__ __forceinline__ void compute_pk(const float acc1[2][4][4], const float acc2[2][4][4],
    const float* __restrict__ mask, const float* __restrict__ bb1, const float* __restrict__ bb2,
    int row0, int wm, int wn, int gid, int tig, uint32_t pk[32]){
  #pragma unroll
  for (int t=0;t<2;t++){
    int rA = wm*32 + t*16 + gid;
    int rB = rA + 8;
    float mvA = mask[row0 + rA], mvB = mask[row0 + rB];
    #pragma unroll
    for (int u=0;u<4;u++){
      int colb = wn*32 + u*8 + 2*tig;
      float2 b1v = *reinterpret_cast<const float2*>(&bb1[colb]);
      float2 b2v = *reinterpret_cast<const float2*>(&bb2[colb]);
      float v0 = mvA*(acc1[t][u][0]+b1v.x)*fsig(acc2[t][u][0]+b2v.x);
      float v1 = mvA*(acc1[t][u][1]+b1v.y)*fsig(acc2[t][u][1]+b2v.y);
      float v2 = mvB*(acc1[t][u][2]+b1v.x)*fsig(acc2[t][u][2]+b2v.x);
      float v3 = mvB*(acc1[t][u][3]+b1v.y)*fsig(acc2[t][u][3]+b2v.y);
      pk[t*16+u*4+0] = pack_hilo(v0);
      pk[t*16+u*4+1] = pack_hilo(v1);
      pk[t*16+u*4+2] = pack_hilo(v2);
      pk[t*16+u*4+3] = pack_hilo(v3);
    }
  }
}

// single-pass packed epilogue store
__device__ __forceinline__ void epi_store_1p(const uint32_t pk[32], uint32_t* __restrict__ ebuf,
    __nv_bfloat16* __restrict__ ghi, __nv_bfloat16* __restrict__ glo,
    int row0, int tid, int wm, int wn, int gid, int tig){
  #pragma unroll
  for (int t=0;t<2;t++){
    int rA = wm*32 + t*16 + gid;
    int rB = rA + 8;
    #pragma unroll
    for (int u=0;u<4;u++){
      int cl = wn*32 + u*8 + 2*tig;
      ebuf[ cl   *LDE + rA] = pk[t*16+u*4+0];
      ebuf[(cl+1)*LDE + rA] = pk[t*16+u*4+1];
      ebuf[ cl   *LDE + rB] = pk[t*16+u*4+2];
      ebuf[(cl+1)*LDE + rB] = pk[t*16+u*4+3];
    }
  }
  __syncthreads();
  {
    int rb = tid & 15;
    int cb = tid >> 4;            // 0..31
    #pragma unroll
    for (int p=0;p<4;p++){
      int cl = cb + 32*p;
      #pragma unroll
      for (int h=0; h<2; h++){
        int rq = rb + 16*h;
        uint4 w = *reinterpret_cast<const uint4*>(&ebuf[cl*LDE + rq*4]);
        uint32_t hi01 = prmt_(w.x, w.y, 0x5410u);
        uint32_t hi23 = prmt_(w.z, w.w, 0x5410u);
        uint32_t lo01 = prmt_(w.x, w.y, 0x7632u);
        uint32_t lo23 = prmt_(w.z, w.w, 0x7632u);
        size_t base = (size_t)cl*NROWS + row0 + rq*4;
        *reinterpret_cast<uint2*>(&ghi[base]) = make_uint2(hi01, hi23);
        *reinterpret_cast<uint2*>(&glo[base]) = make_uint2(lo01, lo23);
      }
    }
  }
  __syncthreads();
}

__global__ __launch_bounds__(512) void proj_all_kernel(
    const float* __restrict__ act, const float* __restrict__ lng, const float* __restrict__ lnb,
    const float* __restrict__ mask,
    const float* __restrict__ Wl,  const float* __restrict__ bl,
    const float* __restrict__ Wgl, const float* __restrict__ bgl,
    const float* __restrict__ Wr,  const float* __restrict__ br,
    const float* __restrict__ Wgr, const float* __restrict__ bgr,
    const float* __restrict__ Wg,  const float* __restrict__ bg,
    __nv_bfloat16* __restrict__ gLh, __nv_bfloat16* __restrict__ gLl,
    __nv_bfloat16* __restrict__ gRh, __nv_bfloat16* __restrict__ gRl,
    float* __restrict__ gate){
  extern __shared__ uint32_t sm[];
  uint32_t* xs   = sm;
  uint32_t* w1   = sm + XS_WORDS;
  uint32_t* w2   = w1 + W_WORDS;
  int tid  = threadIdx.x;
  int row0 = blockIdx.x * 128;
  int kv   = tid & 31;

  // ---- fused staging: act LDG + in-register LN + tf32 STS; W1/W2 via reg roundtrip ----
  {
    uint4 va[8];
    #pragma unroll
    for (int it=0; it<8; ++it){
      int r = (tid>>5) + it*16;
      va[it] = *reinterpret_cast<const uint4*>(&act[(size_t)(row0+r)*CDIM + kv*4]);
    }
    uint4 wA[8], wB[8];
    ldgW(Wl,  tid, wA);
    ldgW(Wgl, tid, wB);
    float4 g4 = *reinterpret_cast<const float4*>(&lng[kv*4]);
    float4 b4 = *reinterpret_cast<const float4*>(&lnb[kv*4]);
    #pragma unroll
    for (int it=0; it<8; ++it){
      int r = (tid>>5) + it*16;
      float4 v = *reinterpret_cast<const float4*>(&va[it]);
      float s  = v.x + v.y + v.z + v.w;
      float s2 = v.x*v.x + v.y*v.y + v.z*v.z + v.w*v.w;
      #pragma unroll
      for (int off=16; off>0; off>>=1){
        s  += __shfl_xor_sync(0xffffffffu, s,  off);
        s2 += __shfl_xor_sync(0xffffffffu, s2, off);
      }
      float mu = s * (1.f/128.f);
      float rs = rsqrtf(s2*(1.f/128.f) - mu*mu + EPSV);
      uint4 t;
      t.x = tf32_rna((v.x-mu)*rs*g4.x + b4.x);
      t.y = tf32_rna((v.y-mu)*rs*g4.y + b4.y);
      t.z = tf32_rna((v.z-mu)*rs*g4.z + b4.z);
      t.w = tf32_rna((v.w-mu)*rs*g4.w + b4.w);
      *reinterpret_cast<uint4*>(&xs[r*LDX + kv*4]) = t;
    }
    stsW(wA, tid, w1);
    stsW(wB, tid, w2);
  }
  __syncthreads();

  int lane = tid&31, wid = tid>>5;
  int wm = wid>>2, wn = wid&3;
  int gid = lane>>2, tig = lane&3;

  float acc1[2][4][4], acc2[2][4][4];
  uint32_t pk[32];

  // ---- GEMM 1: left (dual) ----
  #pragma unroll
  for (int t=0;t<2;t++)
    #pragma unroll
    for (int u=0;u<4;u++)
      #pragma unroll
      for (int r=0;r<4;r++){ acc1[t][u][r]=0.f; acc2[t][u][r]=0.f; }
  gemm_pair(xs, w1, w2, wm, wn, gid, tig, acc1, acc2, true);
  compute_pk(acc1, acc2, mask, bl, bgl, row0, wm, wn, gid, tig, pk);
  __syncthreads();
  {
    uint4 wA[8], wB[8];
    ldgW(Wr,  tid, wA);
    ldgW(Wgr, tid, wB);
    epi_store_1p(pk, w1, gLh, gLl, row0, tid, wm, wn, gid, tig);
    stsW(wA, tid, w1);
    stsW(wB, tid, w2);
  }
  __syncthreads();

  // ---- GEMM 2: right (dual) ----
  #pragma unroll
  for (int t=0;t<2;t++)
    #pragma unroll
    for (int u=0;u<4;u++)
      #pragma unroll
      for (int r=0;r<4;r++){ acc1[t][u][r]=0.f; acc2[t][u][r]=0.f; }
  gemm_pair(xs, w1, w2, wm, wn, gid, tig, acc1, acc2, true);
  compute_pk(acc1, acc2, mask, br, bgr, row0, wm, wn, gid, tig, pk);
  __syncthreads();
  {
    uint4 wA[8];
    ldgW(Wg, tid, wA);
    epi_store_1p(pk, w1, gRh, gRl, row0, tid, wm, wn, gid, tig);
    stsW(wA, tid, w1);
  }
  __syncthreads();

  // ---- GEMM 3: gate (single) ----
  #pragma unroll
  for (int t=0;t<2;t++)
    #pragma unroll
    for (int u=0;u<4;u++)
      #pragma unroll
      for (int r=0;r<4;r++) acc1[t][u][r]=0.f;
  gemm_pair(xs, w1, w1, wm, wn, gid, tig, acc1, acc2, false);
  #pragma unroll
  for (int t=0;t<2;t++){
    int rowA = row0 + wm*32 + t*16 + gid;
    int rowB = rowA + 8;
    #pragma unroll
    for (int u=0;u<4;u++){
      int colb = wn*32 + u*8 + 2*tig;
      float b0 = bg[colb], b1 = bg[colb+1];
      float2 oA, oB;
      oA.x = fsig(acc1[t][u][0]+b0);
      oA.y = fsig(acc1[t][u][1]+b1);
      oB.x = fsig(acc1[t][u][2]+b0);
      oB.y = fsig(acc1[t][u][3]+b1);
      *reinterpret_cast<float2*>(&gate[(size_t)rowA*CDIM + colb]) = oA;
      *reinterpret_cast<float2*>(&gate[(size_t)rowB*CDIM + colb]) = oB;
    }
  }
}

// ============== Stage 3: per-channel GEMM, 128x128 tile, pipelined cp.async ==============
// out_c[i][j] = sum_k L_c[i][k]*R_c[j][k]; 3-term bf16 split.
// 512 threads = 4x4 warps, per-warp 32x32; K chunks of 32, 2-stage pipeline.
#define TRI_LDS 40                         /* bf16 stride: 20 words -> conflict-free frags */
#define TRI_ROWBUF (128*TRI_LDS)           /* one matrix buffer, bf16 units */
#define TRI_STAGE  (4*TRI_ROWBUF)          /* Lhi,Llo,Rhi,Rlo */
#define TRI_SMEM   (2*TRI_STAGE*2)         /* 2 stages, bytes = 81920 */
#define TRI_NCH    (NTOK/32)               /* 12 */

__global__ __launch_bounds__(512) void tri_kernel(){
  extern __shared__ __nv_bfloat16 smb[];
  uint32_t sbase = smem_u32(smb);
  int tid = threadIdx.x;
  int c  = blockIdx.z;
  int i0 = blockIdx.x * 128;
  int j0 = blockIdx.y * 128;
  const __nv_bfloat16* gLh = g_Lhi + (size_t)c*NROWS;
  const __nv_bfloat16* gLl = g_Llo + (size_t)c*NROWS;
  const __nv_bfloat16* gRh = g_Rhi + (size_t)c*NROWS;
  const __nv_bfloat16* gRl = g_Rlo + (size_t)c*NROWS;

  int lane = tid&31, wid = tid>>5;
  int wm = wid>>2, wn = wid&3;
  int gid = lane>>2, tig = lane&3;

  // staging map: r = tid>>2 (0..127), s = tid&3 (16B seg of 32-k chunk)
  int sr = tid>>2, sseg = tid&3;
  uint32_t s_off = (uint32_t)(sr*TRI_LDS + sseg*8)*2;   // byte offset within a buffer

  float acc[2][4][4];
  #pragma unroll
  for (int t=0;t<2;t++)
    #pragma unroll
    for (int u=0;u<4;u++)
      #pragma unroll
      for (int r=0;r<4;r++) acc[t][u][r]=0.f;

  // ---- issue loads for one chunk into stage st ----
  auto load_chunk = [&](int kc, int st){
    uint32_t base = sbase + (uint32_t)(st*TRI_STAGE)*2;
    size_t goL = (size_t)(i0+sr)*NTOK + kc*32 + sseg*8;
    size_t goR = (size_t)(j0+sr)*NTOK + kc*32 + sseg*8;
    cp16(base + 0*TRI_ROWBUF*2 + s_off, &gLh[goL]);
    cp16(base + 1*TRI_ROWBUF*2 + s_off, &gLl[goL]);
    cp16(base + 2*TRI_ROWBUF*2 + s_off, &gRh[goR]);
    cp16(base + 3*TRI_ROWBUF*2 + s_off, &gRl[goR]);
    cp_commit();
  };

  load_chunk(0, 0);

  for (int kc=0; kc<TRI_NCH; kc++){
    if (kc+1 < TRI_NCH){
      load_chunk(kc+1, (kc+1)&1);
      cp_wait<1>();
    } else {
      cp_wait<0>();
    }
    __syncthreads();

    const __nv_bfloat16* Lhi = smb + (kc&1)*TRI_STAGE;
    const __nv_bfloat16* Llo = Lhi + TRI_ROWBUF;
    const __nv_bfloat16* Rhi = Lhi + 2*TRI_ROWBUF;
    const __nv_bfloat16* Rlo = Lhi + 3*TRI_ROWBUF;

    #pragma unroll
    for (int ks=0; ks<2; ks++){
      int ko = ks*16;
      uint32_t ah[2][4], al[2][4];
      #pragma unroll
      for (int t=0;t<2;t++){
        int row = wm*32 + t*16 + gid;
        int base = row*TRI_LDS + ko + 2*tig;
        ah[t][0] = *reinterpret_cast<const uint32_t*>(&Lhi[base]);
        ah[t][1] = *reinterpret_cast<const uint32_t*>(&Lhi[base + 8*TRI_LDS]);
        ah[t][2] = *reinterpret_cast<const uint32_t*>(&Lhi[base + 8]);
        ah[t][3] = *reinterpret_cast<const uint32_t*>(&Lhi[base + 8*TRI_LDS + 8]);
        al[t][0] = *reinterpret_cast<const uint32_t*>(&Llo[base]);
        al[t][1] = *reinterpret_cast<const uint32_t*>(&Llo[base + 8*TRI_LDS]);
        al[t][2] = *reinterpret_cast<const uint32_t*>(&Llo[base + 8]);
        al[t][3] = *reinterpret_cast<const uint32_t*>(&Llo[base + 8*TRI_LDS + 8]);
      }
      #pragma unroll
      for (int u=0;u<4;u++){
        int jrow = wn*32 + u*8 + gid;
        int bb = jrow*TRI_LDS + ko + 2*tig;
        uint32_t bh0 = *reinterpret_cast<const uint32_t*>(&Rhi[bb]);
        uint32_t bh1 = *reinterpret_cast<const uint32_t*>(&Rhi[bb + 8]);
        uint32_t bl0 = *reinterpret_cast<const uint32_t*>(&Rlo[bb]);
        uint32_t bl1 = *reinterpret_cast<const uint32_t*>(&Rlo[bb + 8]);
        #pragma unroll
        for (int t=0;t<2;t++){
          mma_bf16(acc[t][u], ah[t], bh0, bh1);
          mma_bf16(acc[t][u], ah[t], bl0, bl1);
          mma_bf16(acc[t][u], al[t], bh0, bh1);
        }
      }
    }
    __syncthreads();   // buffer (kc+1)&1 safe to overwrite next iteration
  }

  float* To = g_tri + (size_t)c*NROWS;
  #pragma unroll
  for (int t=0;t<2;t++){
    int iA = i0 + wm*32 + t*16 + gid;
    int iB = iA + 8;
    #pragma unroll
    for (int u=0;u<4;u++){
      int j = j0 + wn*32 + u*8 + 2*tig;
      float2 vA = {acc[t][u][0], acc[t][u][1]};
      float2 vB = {acc[t][u][2], acc[t][u][3]};
      *reinterpret_cast<float2*>(&To[(size_t)iA*NTOK + j]) = vA;
      *reinterpret_cast<float2*>(&To[(size_t)iB*NTOK + j]) = vB;
    }
  }
}

// ============== Stage 4: LN(tri) @ Wo + bo, * gate (tf32 mma) ==============
#define LDT 129
#define FINAL_SMEM ((128*LDT + XS_WORDS + W_WORDS)*4)
__global__ __launch_bounds__(512) void final_kernel(const float* __restrict__ cg,
                                                    const float* __restrict__ cb,
                                                    const float* __restrict__ Wo,
                                                    const float* __restrict__ bo,
                                                    float* __restrict__ out){
  extern __shared__ uint32_t sm[];
  float*    T  = reinterpret_cast<float*>(sm);
  uint32_t* xs = sm + 128*LDT;
  uint32_t* w  = xs + XS_WORDS;
  __shared__ float p1[4][128], p2[4][128], mu_s[128], rs_s[128];
  int tid  = threadIdx.x;
  int row0 = blockIdx.x * 128;

  #pragma unroll
  for (int it=0; it<8; ++it){
    int slot = tid + it*512;
    int cch = slot >> 5;
    int v4  = slot & 31;
    float4 v = *reinterpret_cast<const float4*>(&g_tri[(size_t)cch*NROWS + row0 + v4*4]);
    T[cch*LDT + v4*4 + 0] = v.x;
    T[cch*LDT + v4*4 + 1] = v.y;
    T[cch*LDT + v4*4 + 2] = v.z;
    T[cch*LDT + v4*4 + 3] = v.w;
    v = *reinterpret_cast<const float4*>(&Wo[cch*CDIM + v4*4]);
    uint4 t; t.x=tf32_rna(v.x); t.y=tf32_rna(v.y); t.z=tf32_rna(v.z); t.w=tf32_rna(v.w);
    *reinterpret_cast<uint4*>(&w[cch*LDW + v4*4]) = t;
  }
  __syncthreads();

  {
    int ij = tid & 127, pp = tid >> 7;
    float s=0.f, s2=0.f;
    #pragma unroll
    for (int k=0;k<32;k++){
      float v = T[(pp*32+k)*LDT + ij];
      s += v; s2 += v*v;
    }
    p1[pp][ij] = s; p2[pp][ij] = s2;
  }
  __syncthreads();
  if (tid < 128){
    float s  = p1[0][tid]+p1[1][tid]+p1[2][tid]+p1[3][tid];
    float s2 = p2[0][tid]+p2[1][tid]+p2[2][tid]+p2[3][tid];
    float mu = s*(1.f/128.f);
    mu_s[tid] = mu;
    rs_s[tid] = rsqrtf(s2*(1.f/128.f) - mu*mu + EPSV);
  }
  __syncthreads();

  #pragma unroll
  for (int it=0; it<8; ++it){
    int slot = tid + it*512;
    int r  = slot & 127;
    int cq = slot >> 7;
    float mu = mu_s[r], rs = rs_s[r];
    uint4 t;
    {
      int c0 = cq*4;
      float v0 = (T[(c0+0)*LDT + r]-mu)*rs*cg[c0+0] + cb[c0+0];
      float v1 = (T[(c0+1)*LDT + r]-mu)*rs*cg[c0+1] + cb[c0+1];
      float v2 = (T[(c0+2)*LDT + r]-mu)*rs*cg[c0+2] + cb[c0+2];
      float v3 = (T[(c0+3)*LDT + r]-mu)*rs*cg[c0+3] + cb[c0+3];
      t.x=tf32_rna(v0); t.y=tf32_rna(v1); t.z=tf32_rna(v2); t.w=tf32_rna(v3);
    }
    *reinterpret_cast<uint4*>(&xs[r*LDX + cq*4]) = t;
  }
  __syncthreads();

  int lane = tid&31, wid = tid>>5;
  int wm = wid>>2, wn = wid&3;
  int gid = lane>>2, tig = lane&3;

  float acc[2][4][4], accd[2][4][4];
  #pragma unroll
  for (int t=0;t<2;t++)
    #pragma unroll
    for (int u=0;u<4;u++)
      #pragma unroll
      for (int r=0;r<4;r++) acc[t][u][r]=0.f;

  gemm_pair(xs, w, w, wm, wn, gid, tig, acc, accd, false);

  #pragma unroll
  for (int t=0;t<2;t++){
    int rowA = row0 + wm*32 + t*16 + gid;
    int rowB = rowA + 8;
    #pragma unroll
    for (int u=0;u<4;u++){
      int colb = wn*32 + u*8 + 2*tig;
      float bo0 = bo[colb], bo1 = bo[colb+1];
      float2 gA = *reinterpret_cast<const float2*>(&g_gate[(size_t)rowA*CDIM + colb]);
      float2 gB = *reinterpret_cast<const float2*>(&g_gate[(size_t)rowB*CDIM + colb]);
      float2 oA, oB;
      oA.x = (acc[t][u][0]+bo0)*gA.x;
      oA.y = (acc[t][u][1]+bo1)*gA.y;
      oB.x = (acc[t][u][2]+bo0)*gB.x;
      oB.y = (acc[t][u][3]+bo1)*gB.y;
      *reinterpret_cast<float2*>(&out[(size_t)rowA*CDIM + colb]) = oA;
      *reinterpret_cast<float2*>(&out[(size_t)rowB*CDIM + colb]) = oB;
    }
  }
}

extern "C" void kernel_launch(void* const* d_in, const int* in_sizes, int n_in,
                              void* d_out, int out_size) {
  const float* act  = (const float*)d_in[0];
  const float* mask = (const float*)d_in[1];
  const float* ln_g = (const float*)d_in[2];
  const float* ln_b = (const float*)d_in[3];
  const float* Wl   = (const float*)d_in[4];
  const float* bl   = (const float*)d_in[5];
  const float* Wr   = (const float*)d_in[6];
  const float* br   = (const float*)d_in[7];
  const float* Wgl  = (const float*)d_in[8];
  const float* bgl  = (const float*)d_in[9];
  const float* Wgr  = (const float*)d_in[10];
  const float* bgr  = (const float*)d_in[11];
  const float* cg   = (const float*)d_in[12];
  const float* cb   = (const float*)d_in[13];
  const float* Wo   = (const float*)d_in[14];
  const float* bo   = (const float*)d_in[15];
  const float* Wg   = (const float*)d_in[16];
  const float* bg   = (const float*)d_in[17];
  float* out = (float*)d_out;

  __nv_bfloat16 *dLh=nullptr, *dLl=nullptr, *dRh=nullptr, *dRl=nullptr;
  float *dGate=nullptr;
  cudaGetSymbolAddress((void**)&dLh, g_Lhi);
  cudaGetSymbolAddress((void**)&dLl, g_Llo);
  cudaGetSymbolAddress((void**)&dRh, g_Rhi);
  cudaGetSymbolAddress((void**)&dRl, g_Rlo);
  cudaGetSymbolAddress((void**)&dGate, g_gate);

  cudaFuncSetAttribute(proj_all_kernel, cudaFuncAttributeMaxDynamicSharedMemorySize, PROJALL_SMEM);
  cudaFuncSetAttribute(tri_kernel,      cudaFuncAttributeMaxDynamicSharedMemorySize, TRI_SMEM);
  cudaFuncSetAttribute(final_kernel,    cudaFuncAttributeMaxDynamicSharedMemorySize, FINAL_SMEM);

  proj_all_kernel<<<NROWS/128, 512, PROJALL_SMEM>>>(act, ln_g, ln_b, mask,
      Wl, bl, Wgl, bgl, Wr, br, Wgr, bgr, Wg, bg,
      dLh, dLl, dRh, dRl, dGate);
  tri_kernel<<<dim3(NTOK/128, NTOK/128, CDIM), 512, TRI_SMEM>>>();
  final_kernel<<<NROWS/128, 512, FINAL_SMEM>>>(cg, cb, Wo, bo, out);
}

// round 11
// speedup vs baseline: 1.0136x; 1.0136x over previous
#include <cuda_runtime.h>
#include <cuda_bf16.h>
#include <cstdint>
#include <math.h>

#define NTOK 384
#define CDIM 128
#define NROWS (NTOK*NTOK)   /* 147456 */
#define EPSV 1e-5f

// Scratch (no cudaMalloc allowed)
__device__ float g_gate[(size_t)NROWS*CDIM];
__device__ float g_tri [(size_t)NROWS*CDIM];           // [c][i*384+j]
__device__ __nv_bfloat16 g_Lhi[(size_t)CDIM*NROWS];    // [c][i*384+k]
__device__ __nv_bfloat16 g_Llo[(size_t)CDIM*NROWS];
__device__ __nv_bfloat16 g_Rhi[(size_t)CDIM*NROWS];    // [c][j*384+k]
__device__ __nv_bfloat16 g_Rlo[(size_t)CDIM*NROWS];

// fast sigmoid: MUFU.EX2 + MUFU.RCP path (rel err ~2^-21, tolerance is 1e-3)
__device__ __forceinline__ float fsig(float z){
  return __fdividef(1.f, 1.f + __expf(-z));
}

__device__ __forceinline__ uint32_t tf32_rna(float f){
  uint32_t r; asm("cvt.rna.tf32.f32 %0, %1;" : "=r"(r) : "f"(f)); return r;
}
__device__ __forceinline__ uint32_t prmt_(uint32_t a, uint32_t b, uint32_t s){
  uint32_t d; asm("prmt.b32 %0,%1,%2,%3;" : "=r"(d) : "r"(a), "r"(b), "r"(s)); return d;
}
__device__ __forceinline__ uint32_t pack_hilo(float v){
  __nv_bfloat16 h = __float2bfloat16(v);
  float rem = v - __bfloat162float(h);
  __nv_bfloat16 l = __float2bfloat16(rem);
  uint16_t hb = *reinterpret_cast<uint16_t*>(&h);
  uint16_t lb = *reinterpret_cast<uint16_t*>(&l);
  return (uint32_t)hb | ((uint32_t)lb << 16);
}
__device__ __forceinline__ uint32_t smem_u32(const void* p){
  uint32_t a;
  asm("{ .reg .u64 t; cvta.to.shared.u64 t, %1; cvt.u32.u64 %0, t; }" : "=r"(a) : "l"(p));
  return a;
}
__device__ __forceinline__ void cp16(uint32_t dst_smem, const void* src){
  asm volatile("cp.async.ca.shared.global [%0], [%1], 16;" :: "r"(dst_smem), "l"(src));
}
__device__ __forceinline__ void cp_commit(){
  asm volatile("cp.async.commit_group;");
}
template<int N>
__device__ __forceinline__ void cp_wait(){
  asm volatile("cp.async.wait_group %0;" :: "n"(N));
}

// m16n8k8 tf32 mma (sm_80 base ISA)
__device__ __forceinline__ void mma_tf32(float& d0, float& d1, float& d2, float& d3,
                                         uint32_t a0, uint32_t a1, uint32_t a2, uint32_t a3,
                                         uint32_t b0, uint32_t b1){
  asm volatile(
    "mma.sync.aligned.m16n8k8.row.col.f32.tf32.tf32.f32 "
    "{%0,%1,%2,%3}, {%4,%5,%6,%7}, {%8,%9}, {%0,%1,%2,%3};"
    : "+f"(d0), "+f"(d1), "+f"(d2), "+f"(d3)
    : "r"(a0), "r"(a1), "r"(a2), "r"(a3), "r"(b0), "r"(b1));
}

// m16n8k16 bf16 mma (sm_80 base ISA)
__device__ __forceinline__ void mma_bf16(float* d, const uint32_t* a, uint32_t b0, uint32_t b1){
  asm volatile(
    "mma.sync.aligned.m16n8k16.row.col.f32.bf16.bf16.f32 "
    "{%0,%1,%2,%3}, {%4,%5,%6,%7}, {%8,%9}, {%0,%1,%2,%3};"
    : "+f"(d[0]), "+f"(d[1]), "+f"(d[2]), "+f"(d[3])
    : "r"(a[0]), "r"(a[1]), "r"(a[2]), "r"(a[3]), "r"(b0), "r"(b1));
}

// ================= fused LN + 5 projections =================
#define LDX 132
#define LDW 136
#define LDE 132
#define XS_WORDS (128*LDX)
#define W_WORDS  (128*LDW)
#define PROJALL_SMEM ((XS_WORDS + 2*W_WORDS)*4)

// GEMM-pair mainloop: acc1 += xs@w1, (dual) acc2 += xs@w2
__device__ __forceinline__ void gemm_pair(const uint32_t* __restrict__ xs,
                                          const uint32_t* __restrict__ w1,
                                          const uint32_t* __restrict__ w2,
                                          int wm, int wn, int gid, int tig,
                                          float acc1[2][4][4], float acc2[2][4][4],
                                          bool dual){
  const uint32_t* xa  = xs + (wm*32 + gid)*LDX + tig;
  const uint32_t* wb1 = w1 + tig*LDW + wn*32 + gid;
  const uint32_t* wb2 = w2 + tig*LDW + wn*32 + gid;
  #pragma unroll
  for (int kc=0; kc<16; kc++){
    uint32_t a[2][4];
    #pragma unroll
    for (int t=0;t<2;t++){
      const uint32_t* p = xa + t*16*LDX + kc*8;
      a[t][0] = p[0];
      a[t][1] = p[8*LDX];
      a[t][2] = p[4];
      a[t][3] = p[8*LDX + 4];
    }
    #pragma unroll
    for (int u=0;u<4;u++){
      const uint32_t* q1 = wb1 + kc*8*LDW + u*8;
      uint32_t b10 = q1[0], b11 = q1[4*LDW];
      #pragma unroll
      for (int t=0;t<2;t++)
        mma_tf32(acc1[t][u][0],acc1[t][u][1],acc1[t][u][2],acc1[t][u][3],
                 a[t][0],a[t][1],a[t][2],a[t][3], b10,b11);
      if (dual){
        const uint32_t* q2 = wb2 + kc*8*LDW + u*8;
        uint32_t b20 = q2[0], b21 = q2[4*LDW];
        #pragma unroll
        for (int t=0;t<2;t++)
          mma_tf32(acc2[t][u][0],acc2[t][u][1],acc2[t][u][2],acc2[t][u][3],
                   a[t][0],a[t][1],a[t][2],a[t][3], b20,b21);
      }
    }
  }
}

// LDG one 128x128 W into registers (raw fp32 bits)
__device__ __forceinline__ void ldgW(const float* __restrict__ W, int tid, uint4 w[8]){
  #pragma unroll
  for (int it=0; it<8; ++it){
    int slot = tid + it*512;
    int r  = slot >> 5;
    int kv = slot & 31;
    w[it] = *reinterpret_cast<const uint4*>(&W[r*CDIM + kv*4]);
  }
}
// cvt tf32 + STS into a W smem buffer
__device__ __forceinline__ void stsW(const uint4 w[8], int tid, uint32_t* __restrict__ dst){
  #pragma unroll
  for (int it=0; it<8; ++it){
    int slot = tid + it*512;
    int r  = slot >> 5;
    int kv = slot & 31;
    float4 v = *reinterpret_cast<const float4*>(&w[it]);
    uint4 t; t.x=tf32_rna(v.x); t.y=tf32_rna(v.y); t.z=tf32_rna(v.z); t.w=tf32_rna(v.w);
    *reinterpret_cast<uint4*>(&dst[r*LDW + kv*4]) = t;
  }
}

// bias+sigmoid+mask -> (hi,lo) packed words
__device__ __forceinline__ void compute_pk(const float acc1[2][4][4], const float acc2[2][4][4],
    const float* __restrict__ mask, const float* __restrict__ bb1, const float* __restrict__ bb2,
    int row0, int wm, int wn, int gid, int tig, uint32_t pk[32]){
  #pragma unroll
  for (int t=0;t<2;t++){
    int rA = wm*32 + t*16 + gid;
    int rB = rA + 8;
    float mvA = mask[row0 + rA], mvB = mask[row0 + rB];
    #pragma unroll
    for (int u=0;u<4;u++){
      int colb = wn*32 + u*8 + 2*tig;
      float2 b1v = *reinterpret_cast<const float2*>(&bb1[colb]);
      float2 b2v = *reinterpret_cast<const float2*>(&bb2[colb]);
      float v0 = mvA*(acc1[t][u][0]+b1v.x)*fsig(acc2[t][u][0]+b2v.x);
      float v1 = mvA*(acc1[t][u][1]+b1v.y)*fsig(acc2[t][u][1]+b2v.y);
      float v2 = mvB*(acc1[t][u][2]+b1v.x)*fsig(acc2[t][u][2]+b2v.x);
      float v3 = mvB*(acc1[t][u][3]+b1v.y)*fsig(acc2[t][u][3]+b2v.y);
      pk[t*16+u*4+0] = pack_hilo(v0);
      pk[t*16+u*4+1] = pack_hilo(v1);
      pk[t*16+u*4+2] = pack_hilo(v2);
      pk[t*16+u*4+3] = pack_hilo(v3);
    }
  }
}

// single-pass packed epilogue store
__device__ __forceinline__ void epi_store_1p(const uint32_t pk[32], uint32_t* __restrict__ ebuf,
    __nv_bfloat16* __restrict__ ghi, __nv_bfloat16* __restrict__ glo,
    int row0, int tid, int wm, int wn, int gid, int tig){
  #pragma unroll
  for (int t=0;t<2;t++){
    int rA = wm*32 + t*16 + gid;
    int rB = rA + 8;
    #pragma unroll
    for (int u=0;u<4;u++){
      int cl = wn*32 + u*8 + 2*tig;
      ebuf[ cl   *LDE + rA] = pk[t*16+u*4+0];
      ebuf[(cl+1)*LDE + rA] = pk[t*16+u*4+1];
      ebuf[ cl   *LDE + rB] = pk[t*16+u*4+2];
      ebuf[(cl+1)*LDE + rB] = pk[t*16+u*4+3];
    }
  }
  __syncthreads();
  {
    int rb = tid & 15;
    int cb = tid >> 4;            // 0..31
    #pragma unroll
    for (int p=0;p<4;p++){
      int cl = cb + 32*p;
      #pragma unroll
      for (int h=0; h<2; h++){
        int rq = rb + 16*h;
        uint4 w = *reinterpret_cast<const uint4*>(&ebuf[cl*LDE + rq*4]);
        uint32_t hi01 = prmt_(w.x, w.y, 0x5410u);
        uint32_t hi23 = prmt_(w.z, w.w, 0x5410u);
        uint32_t lo01 = prmt_(w.x, w.y, 0x7632u);
        uint32_t lo23 = prmt_(w.z, w.w, 0x7632u);
        size_t base = (size_t)cl*NROWS + row0 + rq*4;
        *reinterpret_cast<uint2*>(&ghi[base]) = make_uint2(hi01, hi23);
        *reinterpret_cast<uint2*>(&glo[base]) = make_uint2(lo01, lo23);
      }
    }
  }
  __syncthreads();
}

__global__ __launch_bounds__(512) void proj_all_kernel(
    const float* __restrict__ act, const float* __restrict__ lng, const float* __restrict__ lnb,
    const float* __restrict__ mask,
    const float* __restrict__ Wl,  const float* __restrict__ bl,
    const float* __restrict__ Wgl, const float* __restrict__ bgl,
    const float* __restrict__ Wr,  const float* __restrict__ br,
    const float* __restrict__ Wgr, const float* __restrict__ bgr,
    const float* __restrict__ Wg,  const float* __restrict__ bg,
    __nv_bfloat16* __restrict__ gLh, __nv_bfloat16* __restrict__ gLl,
    __nv_bfloat16* __restrict__ gRh, __nv_bfloat16* __restrict__ gRl,
    float* __restrict__ gate){
  extern __shared__ uint32_t sm[];
  uint32_t* xs   = sm;
  uint32_t* w1   = sm + XS_WORDS;
  uint32_t* w2   = w1 + W_WORDS;
  int tid  = threadIdx.x;
  int row0 = blockIdx.x * 128;
  int kv   = tid & 31;

  // ---- fused staging: act LDG + in-register LN + tf32 STS; W1/W2 via reg roundtrip ----
  {
    uint4 va[8];
    #pragma unroll
    for (int it=0; it<8; ++it){
      int r = (tid>>5) + it*16;
      va[it] = *reinterpret_cast<const uint4*>(&act[(size_t)(row0+r)*CDIM + kv*4]);
    }
    uint4 wA[8], wB[8];
    ldgW(Wl,  tid, wA);
    ldgW(Wgl, tid, wB);
    float4 g4 = *reinterpret_cast<const float4*>(&lng[kv*4]);
    float4 b4 = *reinterpret_cast<const float4*>(&lnb[kv*4]);
    #pragma unroll
    for (int it=0; it<8; ++it){
      int r = (tid>>5) + it*16;
      float4 v = *reinterpret_cast<const float4*>(&va[it]);
      float s  = v.x + v.y + v.z + v.w;
      float s2 = v.x*v.x + v.y*v.y + v.z*v.z + v.w*v.w;
      #pragma unroll
      for (int off=16; off>0; off>>=1){
        s  += __shfl_xor_sync(0xffffffffu, s,  off);
        s2 += __shfl_xor_sync(0xffffffffu, s2, off);
      }
      float mu = s * (1.f/128.f);
      float rs = rsqrtf(s2*(1.f/128.f) - mu*mu + EPSV);
      uint4 t;
      t.x = tf32_rna((v.x-mu)*rs*g4.x + b4.x);
      t.y = tf32_rna((v.y-mu)*rs*g4.y + b4.y);
      t.z = tf32_rna((v.z-mu)*rs*g4.z + b4.z);
      t.w = tf32_rna((v.w-mu)*rs*g4.w + b4.w);
      *reinterpret_cast<uint4*>(&xs[r*LDX + kv*4]) = t;
    }
    stsW(wA, tid, w1);
    stsW(wB, tid, w2);
  }
  __syncthreads();

  int lane = tid&31, wid = tid>>5;
  int wm = wid>>2, wn = wid&3;
  int gid = lane>>2, tig = lane&3;

  float acc1[2][4][4], acc2[2][4][4];
  uint32_t pk[32];

  // ---- GEMM 1: left (dual) ----
  #pragma unroll
  for (int t=0;t<2;t++)
    #pragma unroll
    for (int u=0;u<4;u++)
      #pragma unroll
      for (int r=0;r<4;r++){ acc1[t][u][r]=0.f; acc2[t][u][r]=0.f; }
  gemm_pair(xs, w1, w2, wm, wn, gid, tig, acc1, acc2, true);
  compute_pk(acc1, acc2, mask, bl, bgl, row0, wm, wn, gid, tig, pk);
  __syncthreads();
  {
    uint4 wA[8], wB[8];
    ldgW(Wr,  tid, wA);
    ldgW(Wgr, tid, wB);
    epi_store_1p(pk, w1, gLh, gLl, row0, tid, wm, wn, gid, tig);
    stsW(wA, tid, w1);
    stsW(wB, tid, w2);
  }
  __syncthreads();

  // ---- GEMM 2: right (dual) ----
  #pragma unroll
  for (int t=0;t<2;t++)
    #pragma unroll
    for (int u=0;u<4;u++)
      #pragma unroll
      for (int r=0;r<4;r++){ acc1[t][u][r]=0.f; acc2[t][u][r]=0.f; }
  gemm_pair(xs, w1, w2, wm, wn, gid, tig, acc1, acc2, true);
  compute_pk(acc1, acc2, mask, br, bgr, row0, wm, wn, gid, tig, pk);
  __syncthreads();
  {
    uint4 wA[8];
    ldgW(Wg, tid, wA);
    epi_store_1p(pk, w1, gRh, gRl, row0, tid, wm, wn, gid, tig);
    stsW(wA, tid, w1);
  }
  __syncthreads();

  // ---- GEMM 3: gate (single) ----
  #pragma unroll
  for (int t=0;t<2;t++)
    #pragma unroll
    for (int u=0;u<4;u++)
      #pragma unroll
      for (int r=0;r<4;r++) acc1[t][u][r]=0.f;
  gemm_pair(xs, w1, w1, wm, wn, gid, tig, acc1, acc2, false);
  #pragma unroll
  for (int t=0;t<2;t++){
    int rowA = row0 + wm*32 + t*16 + gid;
    int rowB = rowA + 8;
    #pragma unroll
    for (int u=0;u<4;u++){
      int colb = wn*32 + u*8 + 2*tig;
      float b0 = bg[colb], b1 = bg[colb+1];
      float2 oA, oB;
      oA.x = fsig(acc1[t][u][0]+b0);
      oA.y = fsig(acc1[t][u][1]+b1);
      oB.x = fsig(acc1[t][u][2]+b0);
      oB.y = fsig(acc1[t][u][3]+b1);
      *reinterpret_cast<float2*>(&gate[(size_t)rowA*CDIM + colb]) = oA;
      *reinterpret_cast<float2*>(&gate[(size_t)rowB*CDIM + colb]) = oB;
    }
  }
}

// ============== Stage 3: per-channel GEMM via bf16-split mma ==============
// 64x128 tile (R9 config, 2 CTAs/SM) + 2-stage cp.async pipeline, 32-k chunks.
#define TRI_LDS 40                          /* bf16 stride: 20 words -> conflict-free frags */
#define TRI_LBUF (64*TRI_LDS)
#define TRI_RBUF (128*TRI_LDS)
#define TRI_STAGE (2*TRI_LBUF + 2*TRI_RBUF) /* Lhi,Llo,Rhi,Rlo bf16 units = 15360 */
#define TRI_SMEM  (2*TRI_STAGE*2)           /* 2 stages, bytes = 61440 */
#define TRI_NCH   (NTOK/32)                 /* 12 */

__global__ __launch_bounds__(256, 2) void tri_kernel(){
  extern __shared__ __nv_bfloat16 smb[];
  uint32_t sbase = smem_u32(smb);
  int tid = threadIdx.x;
  int c  = blockIdx.z;
  int i0 = blockIdx.x * 64;
  int j0 = blockIdx.y * 128;
  const __nv_bfloat16* gLh = g_Lhi + (size_t)c*NROWS;
  const __nv_bfloat16* gLl = g_Llo + (size_t)c*NROWS;
  const __nv_bfloat16* gRh = g_Rhi + (size_t)c*NROWS;
  const __nv_bfloat16* gRl = g_Rlo + (size_t)c*NROWS;

  int lane = tid&31, wid = tid>>5;
  int wm = wid>>2, wn = wid&3;            // 2x4 warp grid
  int gid = lane>>2, tig = lane&3;

  // staging map: 32-k chunk = 4 x 16B segs per row
  int sr = tid>>2, sseg = tid&3;
  uint32_t so = (uint32_t)(sr*TRI_LDS + sseg*8)*2;

  float acc[2][4][4];
  #pragma unroll
  for (int t=0;t<2;t++)
    #pragma unroll
    for (int u=0;u<4;u++)
      #pragma unroll
      for (int r=0;r<4;r++) acc[t][u][r]=0.f;

  auto load_chunk = [&](int kc, int st){
    uint32_t base = sbase + (uint32_t)(st*TRI_STAGE)*2;
    // L: 64 rows x 32 k (sr covers 0..63)
    {
      size_t go = (size_t)(i0+sr)*NTOK + kc*32 + sseg*8;
      cp16(base + so, &gLh[go]);
      cp16(base + TRI_LBUF*2 + so, &gLl[go]);
    }
    // R: 128 rows x 32 k (two iterations)
    #pragma unroll
    for (int it=0; it<2; ++it){
      int r = sr + it*64;
      size_t go = (size_t)(j0+r)*NTOK + kc*32 + sseg*8;
      uint32_t sor = (uint32_t)(r*TRI_LDS + sseg*8)*2;
      cp16(base + 2*TRI_LBUF*2 + sor, &gRh[go]);
      cp16(base + 2*TRI_LBUF*2 + TRI_RBUF*2 + sor, &gRl[go]);
    }
    cp_commit();
  };

  load_chunk(0, 0);

  for (int kc=0; kc<TRI_NCH; kc++){
    if (kc+1 < TRI_NCH){
      load_chunk(kc+1, (kc+1)&1);
      cp_wait<1>();
    } else {
      cp_wait<0>();
    }
    __syncthreads();

    const __nv_bfloat16* Lhi = smb + (kc&1)*TRI_STAGE;
    const __nv_bfloat16* Llo = Lhi + TRI_LBUF;
    const __nv_bfloat16* Rhi = Llo + TRI_LBUF;
    const __nv_bfloat16* Rlo = Rhi + TRI_RBUF;

    #pragma unroll
    for (int ks=0; ks<2; ks++){
      int ko = ks*16;
      uint32_t ah[2][4], al[2][4];
      #pragma unroll
      for (int t=0;t<2;t++){
        int row = wm*32 + t*16 + gid;
        int base = row*TRI_LDS + ko + 2*tig;
        ah[t][0] = *reinterpret_cast<const uint32_t*>(&Lhi[base]);
        ah[t][1] = *reinterpret_cast<const uint32_t*>(&Lhi[base + 8*TRI_LDS]);
        ah[t][2] = *reinterpret_cast<const uint32_t*>(&Lhi[base + 8]);
        ah[t][3] = *reinterpret_cast<const uint32_t*>(&Lhi[base + 8*TRI_LDS + 8]);
        al[t][0] = *reinterpret_cast<const uint32_t*>(&Llo[base]);
        al[t][1] = *reinterpret_cast<const uint32_t*>(&Llo[base + 8*TRI_LDS]);
        al[t][2] = *reinterpret_cast<const uint32_t*>(&Llo[base + 8]);
        al[t][3] = *reinterpret_cast<const uint32_t*>(&Llo[base + 8*TRI_LDS + 8]);
      }
      #pragma unroll
      for (int u=0;u<4;u++){
        int jrow = wn*32 + u*8 + gid;
        int bb = jrow*TRI_LDS + ko + 2*tig;
        uint32_t bh0 = *reinterpret_cast<const uint32_t*>(&Rhi[bb]);
        uint32_t bh1 = *reinterpret_cast<const uint32_t*>(&Rhi[bb + 8]);
        uint32_t bl0 = *reinterpret_cast<const uint32_t*>(&Rlo[bb]);
        uint32_t bl1 = *reinterpret_cast<const uint32_t*>(&Rlo[bb + 8]);
        #pragma unroll
        for (int t=0;t<2;t++){
          mma_bf16(acc[t][u], ah[t], bh0, bh1);
          mma_bf16(acc[t][u], ah[t], bl0, bl1);
          mma_bf16(acc[t][u], al[t], bh0, bh1);
        }
      }
    }
    __syncthreads();   // buffer (kc+1)&1 safe to refill next iteration
  }

  float* To = g_tri + (size_t)c*NROWS;
  #pragma unroll
  for (int t=0;t<2;t++){
    int iA = i0 + wm*32 + t*16 + gid;
    int iB = iA + 8;
    #pragma unroll
    for (int u=0;u<4;u++){
      int j = j0 + wn*32 + u*8 + 2*tig;
      float2 vA = {acc[t][u][0], acc[t][u][1]};
      float2 vB = {acc[t][u][2], acc[t][u][3]};
      *reinterpret_cast<float2*>(&To[(size_t)iA*NTOK + j]) = vA;
      *reinterpret_cast<float2*>(&To[(size_t)iB*NTOK + j]) = vB;
    }
  }
}

// ============== Stage 4: LN(tri) @ Wo + bo, * gate (tf32 mma) ==============
#define LDT 129
#define FINAL_SMEM ((128*LDT + XS_WORDS + W_WORDS)*4)
__global__ __launch_bounds__(512) void final_kernel(const float* __restrict__ cg,
                                                    const float* __restrict__ cb,
                                                    const float* __restrict__ Wo,
                                                    const float* __restrict__ bo,
                                                    float* __restrict__ out){
  extern __shared__ uint32_t sm[];
  float*    T  = reinterpret_cast<float*>(sm);
  uint32_t* xs = sm + 128*LDT;
  uint32_t* w  = xs + XS_WORDS;
  __shared__ float p1[4][128], p2[4][128], mu_s[128], rs_s[128];
  int tid  = threadIdx.x;
  int row0 = blockIdx.x * 128;

  #pragma unroll
  for (int it=0; it<8; ++it){
    int slot = tid + it*512;
    int cch = slot >> 5;
    int v4  = slot & 31;
    float4 v = *reinterpret_cast<const float4*>(&g_tri[(size_t)cch*NROWS + row0 + v4*4]);
    T[cch*LDT + v4*4 + 0] = v.x;
    T[cch*LDT + v4*4 + 1] = v.y;
    T[cch*LDT + v4*4 + 2] = v.z;
    T[cch*LDT + v4*4 + 3] = v.w;
    v = *reinterpret_cast<const float4*>(&Wo[cch*CDIM + v4*4]);
    uint4 t; t.x=tf32_rna(v.x); t.y=tf32_rna(v.y); t.z=tf32_rna(v.z); t.w=tf32_rna(v.w);
    *reinterpret_cast<uint4*>(&w[cch*LDW + v4*4]) = t;
  }
  __syncthreads();

  {
    int ij = tid & 127, pp = tid >> 7;
    float s=0.f, s2=0.f;
    #pragma unroll
    for (int k=0;k<32;k++){
      float v = T[(pp*32+k)*LDT + ij];
      s += v; s2 += v*v;
    }
    p1[pp][ij] = s; p2[pp][ij] = s2;
  }
  __syncthreads();
  if (tid < 128){
    float s  = p1[0][tid]+p1[1][tid]+p1[2][tid]+p1[3][tid];
    float s2 = p2[0][tid]+p2[1][tid]+p2[2][tid]+p2[3][tid];
    float mu = s*(1.f/128.f);
    mu_s[tid] = mu;
    rs_s[tid] = rsqrtf(s2*(1.f/128.f) - mu*mu + EPSV);
  }
  __syncthreads();

  #pragma unroll
  for (int it=0; it<8; ++it){
    int slot = tid + it*512;
    int r  = slot & 127;
    int cq = slot >> 7;
    float mu = mu_s[r], rs = rs_s[r];
    uint4 t;
    {
      int c0 = cq*4;
      float v0 = (T[(c0+0)*LDT + r]-mu)*rs*cg[c0+0] + cb[c0+0];
      float v1 = (T[(c0+1)*LDT + r]-mu)*rs*cg[c0+1] + cb[c0+1];
      float v2 = (T[(c0+2)*LDT + r]-mu)*rs*cg[c0+2] + cb[c0+2];
      float v3 = (T[(c0+3)*LDT + r]-mu)*rs*cg[c0+3] + cb[c0+3];
      t.x=tf32_rna(v0); t.y=tf32_rna(v1); t.z=tf32_rna(v2); t.w=tf32_rna(v3);
    }
    *reinterpret_cast<uint4*>(&xs[r*LDX + cq*4]) = t;
  }
  __syncthreads();

  int lane = tid&31, wid = tid>>5;
  int wm = wid>>2, wn = wid&3;
  int gid = lane>>2, tig = lane&3;

  float acc[2][4][4], accd[2][4][4];
  #pragma unroll
  for (int t=0;t<2;t++)
    #pragma unroll
    for (int u=0;u<4;u++)
      #pragma unroll
      for (int r=0;r<4;r++) acc[t][u][r]=0.f;

  gemm_pair(xs, w, w, wm, wn, gid, tig, acc, accd, false);

  #pragma unroll
  for (int t=0;t<2;t++){
    int rowA = row0 + wm*32 + t*16 + gid;
    int rowB = rowA + 8;
    #pragma unroll
    for (int u=0;u<4;u++){
      int colb = wn*32 + u*8 + 2*tig;
      float bo0 = bo[colb], bo1 = bo[colb+1];
      float2 gA = *reinterpret_cast<const float2*>(&g_gate[(size_t)rowA*CDIM + colb]);
      float2 gB = *reinterpret_cast<const float2*>(&g_gate[(size_t)rowB*CDIM + colb]);
      float2 oA, oB;
      oA.x = (acc[t][u][0]+bo0)*gA.x;
      oA.y = (acc[t][u][1]+bo1)*gA.y;
      oB.x = (acc[t][u][2]+bo0)*gB.x;
      oB.y = (acc[t][u][3]+bo1)*gB.y;
      *reinterpret_cast<float2*>(&out[(size_t)rowA*CDIM + colb]) = oA;
      *reinterpret_cast<float2*>(&out[(size_t)rowB*CDIM + colb]) = oB;
    }
  }
}

extern "C" void kernel_launch(void* const* d_in, const int* in_sizes, int n_in,
                              void* d_out, int out_size) {
  const float* act  = (const float*)d_in[0];
  const float* mask = (const float*)d_in[1];
  const float* ln_g = (const float*)d_in[2];
  const float* ln_b = (const float*)d_in[3];
  const float* Wl   = (const float*)d_in[4];
  const float* bl   = (const float*)d_in[5];
  const float* Wr   = (const float*)d_in[6];
  const float* br   = (const float*)d_in[7];
  const float* Wgl  = (const float*)d_in[8];
  const float* bgl  = (const float*)d_in[9];
  const float* Wgr  = (const float*)d_in[10];
  const float* bgr  = (const float*)d_in[11];
  const float* cg   = (const float*)d_in[12];
  const float* cb   = (const float*)d_in[13];
  const float* Wo   = (const float*)d_in[14];
  const float* bo   = (const float*)d_in[15];
  const float* Wg   = (const float*)d_in[16];
  const float* bg   = (const float*)d_in[17];
  float* out = (float*)d_out;

  __nv_bfloat16 *dLh=nullptr, *dLl=nullptr, *dRh=nullptr, *dRl=nullptr;
  float *dGate=nullptr;
  cudaGetSymbolAddress((void**)&dLh, g_Lhi);
  cudaGetSymbolAddress((void**)&dLl, g_Llo);
  cudaGetSymbolAddress((void**)&dRh, g_Rhi);
  cudaGetSymbolAddress((void**)&dRl, g_Rlo);
  cudaGetSymbolAddress((void**)&dGate, g_gate);

  cudaFuncSetAttribute(proj_all_kernel, cudaFuncAttributeMaxDynamicSharedMemorySize, PROJALL_SMEM);
  cudaFuncSetAttribute(tri_kernel,      cudaFuncAttributeMaxDynamicSharedMemorySize, TRI_SMEM);
  cudaFuncSetAttribute(final_kernel,    cudaFuncAttributeMaxDynamicSharedMemorySize, FINAL_SMEM);

  proj_all_kernel<<<NROWS/128, 512, PROJALL_SMEM>>>(act, ln_g, ln_b, mask,
      Wl, bl, Wgl, bgl, Wr, br, Wgr, bgr, Wg, bg,
      dLh, dLl, dRh, dRl, dGate);
  tri_kernel<<<dim3(NTOK/64, NTOK/128, CDIM), 256, TRI_SMEM>>>();
  final_kernel<<<NROWS/128, 512, FINAL_SMEM>>>(cg, cb, Wo, bo, out);
}

// round 12
// speedup vs baseline: 1.0680x; 1.0536x over previous
#include <cuda_runtime.h>
#include <cuda_bf16.h>
#include <cstdint>
#include <math.h>

#define NTOK 384
#define CDIM 128
#define NROWS (NTOK*NTOK)   /* 147456 */
#define EPSV 1e-5f

// Scratch (no cudaMalloc allowed)
__device__ float g_gate[(size_t)NROWS*CDIM];
__device__ float g_tri [(size_t)NROWS*CDIM];           // [c][i*384+j]
__device__ __nv_bfloat16 g_Lhi[(size_t)CDIM*NROWS];    // [c][i*384+k]
__device__ __nv_bfloat16 g_Llo[(size_t)CDIM*NROWS];
__device__ __nv_bfloat16 g_Rhi[(size_t)CDIM*NROWS];    // [c][j*384+k]
__device__ __nv_bfloat16 g_Rlo[(size_t)CDIM*NROWS];

// fast sigmoid: MUFU.EX2 + MUFU.RCP path (rel err ~2^-21, tolerance is 1e-3)
__device__ __forceinline__ float fsig(float z){
  return __fdividef(1.f, 1.f + __expf(-z));
}

__device__ __forceinline__ uint32_t tf32_rna(float f){
  uint32_t r; asm("cvt.rna.tf32.f32 %0, %1;" : "=r"(r) : "f"(f)); return r;
}
__device__ __forceinline__ uint32_t prmt_(uint32_t a, uint32_t b, uint32_t s){
  uint32_t d; asm("prmt.b32 %0,%1,%2,%3;" : "=r"(d) : "r"(a), "r"(b), "r"(s)); return d;
}
__device__ __forceinline__ uint32_t pack_hilo(float v){
  __nv_bfloat16 h = __float2bfloat16(v);
  float rem = v - __bfloat162float(h);
  __nv_bfloat16 l = __float2bfloat16(rem);
  uint16_t hb = *reinterpret_cast<uint16_t*>(&h);
  uint16_t lb = *reinterpret_cast<uint16_t*>(&l);
  return (uint32_t)hb | ((uint32_t)lb << 16);
}
__device__ __forceinline__ uint32_t smem_u32(const void* p){
  uint32_t a;
  asm("{ .reg .u64 t; cvta.to.shared.u64 t, %1; cvt.u32.u64 %0, t; }" : "=r"(a) : "l"(p));
  return a;
}
__device__ __forceinline__ void cp16(uint32_t dst_smem, const void* src){
  asm volatile("cp.async.ca.shared.global [%0], [%1], 16;" :: "r"(dst_smem), "l"(src));
}
__device__ __forceinline__ void cp_commit_wait(){
  asm volatile("cp.async.commit_group;");
  asm volatile("cp.async.wait_group 0;");
}

// m16n8k8 tf32 mma (sm_80 base ISA)
__device__ __forceinline__ void mma_tf32(float& d0, float& d1, float& d2, float& d3,
                                         uint32_t a0, uint32_t a1, uint32_t a2, uint32_t a3,
                                         uint32_t b0, uint32_t b1){
  asm volatile(
    "mma.sync.aligned.m16n8k8.row.col.f32.tf32.tf32.f32 "
    "{%0,%1,%2,%3}, {%4,%5,%6,%7}, {%8,%9}, {%0,%1,%2,%3};"
    : "+f"(d0), "+f"(d1), "+f"(d2), "+f"(d3)
    : "r"(a0), "r"(a1), "r"(a2), "r"(a3), "r"(b0), "r"(b1));
}

// m16n8k16 bf16 mma (sm_80 base ISA)
__device__ __forceinline__ void mma_bf16(float* d, const uint32_t* a, uint32_t b0, uint32_t b1){
  asm volatile(
    "mma.sync.aligned.m16n8k16.row.col.f32.bf16.bf16.f32 "
    "{%0,%1,%2,%3}, {%4,%5,%6,%7}, {%8,%9}, {%0,%1,%2,%3};"
    : "+f"(d[0]), "+f"(d[1]), "+f"(d[2]), "+f"(d[3])
    : "r"(a[0]), "r"(a[1]), "r"(a[2]), "r"(a[3]), "r"(b0), "r"(b1));
}

// ================= fused LN + 5 projections =================
#define LDX 132
#define LDW 136
#define LDE 132
#define XS_WORDS (128*LDX)
#define W_WORDS  (128*LDW)
#define PROJALL_SMEM ((XS_WORDS + 2*W_WORDS)*4)

// GEMM-pair mainloop: acc1 += xs@w1, (dual) acc2 += xs@w2
__device__ __forceinline__ void gemm_pair(const uint32_t* __restrict__ xs,
                                          const uint32_t* __restrict__ w1,
                                          const uint32_t* __restrict__ w2,
                                          int wm, int wn, int gid, int tig,
                                          float acc1[2][4][4], float acc2[2][4][4],
                                          bool dual){
  const uint32_t* xa  = xs + (wm*32 + gid)*LDX + tig;
  const uint32_t* wb1 = w1 + tig*LDW + wn*32 + gid;
  const uint32_t* wb2 = w2 + tig*LDW + wn*32 + gid;
  #pragma unroll
  for (int kc=0; kc<16; kc++){
    uint32_t a[2][4];
    #pragma unroll
    for (int t=0;t<2;t++){
      const uint32_t* p = xa + t*16*LDX + kc*8;
      a[t][0] = p[0];
      a[t][1] = p[8*LDX];
      a[t][2] = p[4];
      a[t][3] = p[8*LDX + 4];
    }
    #pragma unroll
    for (int u=0;u<4;u++){
      const uint32_t* q1 = wb1 + kc*8*LDW + u*8;
      uint32_t b10 = q1[0], b11 = q1[4*LDW];
      #pragma unroll
      for (int t=0;t<2;t++)
        mma_tf32(acc1[t][u][0],acc1[t][u][1],acc1[t][u][2],acc1[t][u][3],
                 a[t][0],a[t][1],a[t][2],a[t][3], b10,b11);
      if (dual){
        const uint32_t* q2 = wb2 + kc*8*LDW + u*8;
        uint32_t b20 = q2[0], b21 = q2[4*LDW];
        #pragma unroll
        for (int t=0;t<2;t++)
          mma_tf32(acc2[t][u][0],acc2[t][u][1],acc2[t][u][2],acc2[t][u][3],
                   a[t][0],a[t][1],a[t][2],a[t][3], b20,b21);
      }
    }
  }
}

// LDG one 128x128 W into registers (raw fp32 bits)
__device__ __forceinline__ void ldgW(const float* __restrict__ W, int tid, uint4 w[8]){
  #pragma unroll
  for (int it=0; it<8; ++it){
    int slot = tid + it*512;
    int r  = slot >> 5;
    int kv = slot & 31;
    w[it] = *reinterpret_cast<const uint4*>(&W[r*CDIM + kv*4]);
  }
}
// cvt tf32 + STS into a W smem buffer
__device__ __forceinline__ void stsW(const uint4 w[8], int tid, uint32_t* __restrict__ dst){
  #pragma unroll
  for (int it=0; it<8; ++it){
    int slot = tid + it*512;
    int r  = slot >> 5;
    int kv = slot & 31;
    float4 v = *reinterpret_cast<const float4*>(&w[it]);
    uint4 t; t.x=tf32_rna(v.x); t.y=tf32_rna(v.y); t.z=tf32_rna(v.z); t.w=tf32_rna(v.w);
    *reinterpret_cast<uint4*>(&dst[r*LDW + kv*4]) = t;
  }
}

// bias+sigmoid+mask -> (hi,lo) packed words
__device__ __forceinline__ void compute_pk(const float acc1[2][4][4], const float acc2[2][4][4],
    const float* __restrict__ mask, const float* __restrict__ bb1, const float* __restrict__ bb2,
    int row0, int wm, int wn, int gid, int tig, uint32_t pk[32]){
  #pragma unroll
  for (int t=0;t<2;t++){
    int rA = wm*32 + t*16 + gid;
    int rB = rA + 8;
    float mvA = mask[row0 + rA], mvB = mask[row0 + rB];
    #pragma unroll
    for (int u=0;u<4;u++){
      int colb = wn*32 + u*8 + 2*tig;
      float2 b1v = *reinterpret_cast<const float2*>(&bb1[colb]);
      float2 b2v = *reinterpret_cast<const float2*>(&bb2[colb]);
      float v0 = mvA*(acc1[t][u][0]+b1v.x)*fsig(acc2[t][u][0]+b2v.x);
      float v1 = mvA*(acc1[t][u][1]+b1v.y)*fsig(acc2[t][u][1]+b2v.y);
      float v2 = mvB*(acc1[t][u][2]+b1v.x)*fsig(acc2[t][u][2]+b2v.x);
      float v3 = mvB*(acc1[t][u][3]+b1v.y)*fsig(acc2[t][u][3]+b2v.y);
      pk[t*16+u*4+0] = pack_hilo(v0);
      pk[t*16+u*4+1] = pack_hilo(v1);
      pk[t*16+u*4+2] = pack_hilo(v2);
      pk[t*16+u*4+3] = pack_hilo(v3);
    }
  }
}

// single-pass packed epilogue store
__device__ __forceinline__ void epi_store_1p(const uint32_t pk[32], uint32_t* __restrict__ ebuf,
    __nv_bfloat16* __restrict__ ghi, __nv_bfloat16* __restrict__ glo,
    int row0, int tid, int wm, int wn, int gid, int tig){
  #pragma unroll
  for (int t=0;t<2;t++){
    int rA = wm*32 + t*16 + gid;
    int rB = rA + 8;
    #pragma unroll
    for (int u=0;u<4;u++){
      int cl = wn*32 + u*8 + 2*tig;
      ebuf[ cl   *LDE + rA] = pk[t*16+u*4+0];
      ebuf[(cl+1)*LDE + rA] = pk[t*16+u*4+1];
      ebuf[ cl   *LDE + rB] = pk[t*16+u*4+2];
      ebuf[(cl+1)*LDE + rB] = pk[t*16+u*4+3];
    }
  }
  __syncthreads();
  {
    int rb = tid & 15;
    int cb = tid >> 4;            // 0..31
    #pragma unroll
    for (int p=0;p<4;p++){
      int cl = cb + 32*p;
      #pragma unroll
      for (int h=0; h<2; h++){
        int rq = rb + 16*h;
        uint4 w = *reinterpret_cast<const uint4*>(&ebuf[cl*LDE + rq*4]);
        uint32_t hi01 = prmt_(w.x, w.y, 0x5410u);
        uint32_t hi23 = prmt_(w.z, w.w, 0x5410u);
        uint32_t lo01 = prmt_(w.x, w.y, 0x7632u);
        uint32_t lo23 = prmt_(w.z, w.w, 0x7632u);
        size_t base = (size_t)cl*NROWS + row0 + rq*4;
        *reinterpret_cast<uint2*>(&ghi[base]) = make_uint2(hi01, hi23);
        *reinterpret_cast<uint2*>(&glo[base]) = make_uint2(lo01, lo23);
      }
    }
  }
  __syncthreads();
}

__global__ __launch_bounds__(512) void proj_all_kernel(
    const float* __restrict__ act, const float* __restrict__ lng, const float* __restrict__ lnb,
    const float* __restrict__ mask,
    const float* __restrict__ Wl,  const float* __restrict__ bl,
    const float* __restrict__ Wgl, const float* __restrict__ bgl,
    const float* __restrict__ Wr,  const float* __restrict__ br,
    const float* __restrict__ Wgr, const float* __restrict__ bgr,
    const float* __restrict__ Wg,  const float* __restrict__ bg,
    __nv_bfloat16* __restrict__ gLh, __nv_bfloat16* __restrict__ gLl,
    __nv_bfloat16* __restrict__ gRh, __nv_bfloat16* __restrict__ gRl,
    float* __restrict__ gate){
  extern __shared__ uint32_t sm[];
  uint32_t* xs   = sm;
  uint32_t* w1   = sm + XS_WORDS;
  uint32_t* w2   = w1 + W_WORDS;
  int tid  = threadIdx.x;
  int row0 = blockIdx.x * 128;
  int kv   = tid & 31;

  // ---- fused staging: act LDG + in-register LN + tf32 STS; W1/W2 via reg roundtrip ----
  {
    uint4 va[8];
    #pragma unroll
    for (int it=0; it<8; ++it){
      int r = (tid>>5) + it*16;
      va[it] = *reinterpret_cast<const uint4*>(&act[(size_t)(row0+r)*CDIM + kv*4]);
    }
    uint4 wA[8], wB[8];
    ldgW(Wl,  tid, wA);
    ldgW(Wgl, tid, wB);
    float4 g4 = *reinterpret_cast<const float4*>(&lng[kv*4]);
    float4 b4 = *reinterpret_cast<const float4*>(&lnb[kv*4]);
    #pragma unroll
    for (int it=0; it<8; ++it){
      int r = (tid>>5) + it*16;
      float4 v = *reinterpret_cast<const float4*>(&va[it]);
      float s  = v.x + v.y + v.z + v.w;
      float s2 = v.x*v.x + v.y*v.y + v.z*v.z + v.w*v.w;
      #pragma unroll
      for (int off=16; off>0; off>>=1){
        s  += __shfl_xor_sync(0xffffffffu, s,  off);
        s2 += __shfl_xor_sync(0xffffffffu, s2, off);
      }
      float mu = s * (1.f/128.f);
      float rs = rsqrtf(s2*(1.f/128.f) - mu*mu + EPSV);
      uint4 t;
      t.x = tf32_rna((v.x-mu)*rs*g4.x + b4.x);
      t.y = tf32_rna((v.y-mu)*rs*g4.y + b4.y);
      t.z = tf32_rna((v.z-mu)*rs*g4.z + b4.z);
      t.w = tf32_rna((v.w-mu)*rs*g4.w + b4.w);
      *reinterpret_cast<uint4*>(&xs[r*LDX + kv*4]) = t;
    }
    stsW(wA, tid, w1);
    stsW(wB, tid, w2);
  }
  __syncthreads();

  int lane = tid&31, wid = tid>>5;
  int wm = wid>>2, wn = wid&3;
  int gid = lane>>2, tig = lane&3;

  float acc1[2][4][4], acc2[2][4][4];
  uint32_t pk[32];

  // ---- GEMM 1: left (dual) ----
  #pragma unroll
  for (int t=0;t<2;t++)
    #pragma unroll
    for (int u=0;u<4;u++)
      #pragma unroll
      for (int r=0;r<4;r++){ acc1[t][u][r]=0.f; acc2[t][u][r]=0.f; }
  gemm_pair(xs, w1, w2, wm, wn, gid, tig, acc1, acc2, true);
  compute_pk(acc1, acc2, mask, bl, bgl, row0, wm, wn, gid, tig, pk);
  __syncthreads();
  {
    uint4 wA[8], wB[8];
    ldgW(Wr,  tid, wA);
    ldgW(Wgr, tid, wB);
    epi_store_1p(pk, w1, gLh, gLl, row0, tid, wm, wn, gid, tig);
    stsW(wA, tid, w1);
    stsW(wB, tid, w2);
  }
  __syncthreads();

  // ---- GEMM 2: right (dual) ----
  #pragma unroll
  for (int t=0;t<2;t++)
    #pragma unroll
    for (int u=0;u<4;u++)
      #pragma unroll
      for (int r=0;r<4;r++){ acc1[t][u][r]=0.f; acc2[t][u][r]=0.f; }
  gemm_pair(xs, w1, w2, wm, wn, gid, tig, acc1, acc2, true);
  compute_pk(acc1, acc2, mask, br, bgr, row0, wm, wn, gid, tig, pk);
  __syncthreads();
  {
    uint4 wA[8];
    ldgW(Wg, tid, wA);
    epi_store_1p(pk, w1, gRh, gRl, row0, tid, wm, wn, gid, tig);
    stsW(wA, tid, w1);
  }
  __syncthreads();

  // ---- GEMM 3: gate (single) ----
  #pragma unroll
  for (int t=0;t<2;t++)
    #pragma unroll
    for (int u=0;u<4;u++)
      #pragma unroll
      for (int r=0;r<4;r++) acc1[t][u][r]=0.f;
  gemm_pair(xs, w1, w1, wm, wn, gid, tig, acc1, acc2, false);
  #pragma unroll
  for (int t=0;t<2;t++){
    int rowA = row0 + wm*32 + t*16 + gid;
    int rowB = rowA + 8;
    #pragma unroll
    for (int u=0;u<4;u++){
      int colb = wn*32 + u*8 + 2*tig;
      float b0 = bg[colb], b1 = bg[colb+1];
      float2 oA, oB;
      oA.x = fsig(acc1[t][u][0]+b0);
      oA.y = fsig(acc1[t][u][1]+b1);
      oB.x = fsig(acc1[t][u][2]+b0);
      oB.y = fsig(acc1[t][u][3]+b1);
      *reinterpret_cast<float2*>(&gate[(size_t)rowA*CDIM + colb]) = oA;
      *reinterpret_cast<float2*>(&gate[(size_t)rowB*CDIM + colb]) = oB;
    }
  }
}

// ============== Stage 3: per-channel GEMM via bf16-split mma ==============
// cp.async staging; 64x128 tile; 3 CTAs/SM (smem 55.3KB x3 = 166KB, regs capped 85).
#define TRI_LDS 72
#define TRI_SMEM ((64*TRI_LDS*2 + 128*TRI_LDS*2)*2)
__global__ __launch_bounds__(256, 3) void tri_kernel(){
  extern __shared__ __nv_bfloat16 smb[];
  __nv_bfloat16* Lhi = smb;
  __nv_bfloat16* Llo = smb + 64*TRI_LDS;
  __nv_bfloat16* Rhi = smb + 2*64*TRI_LDS;
  __nv_bfloat16* Rlo = Rhi + 128*TRI_LDS;
  uint32_t sLhi = smem_u32(Lhi);
  uint32_t sLlo = smem_u32(Llo);
  uint32_t sRhi = smem_u32(Rhi);
  uint32_t sRlo = smem_u32(Rlo);
  int tid = threadIdx.x;
  int c  = blockIdx.z;
  int i0 = blockIdx.x * 64;
  int j0 = blockIdx.y * 128;
  const __nv_bfloat16* gLh = g_Lhi + (size_t)c*NROWS;
  const __nv_bfloat16* gLl = g_Llo + (size_t)c*NROWS;
  const __nv_bfloat16* gRh = g_Rhi + (size_t)c*NROWS;
  const __nv_bfloat16* gRl = g_Rlo + (size_t)c*NROWS;

  int lane = tid&31, wid = tid>>5;
  int wm = wid>>2, wn = wid&3;
  int gid = lane>>2, tig = lane&3;

  int sr = tid>>3, sseg = tid&7;

  float acc[2][4][4];
  #pragma unroll
  for (int t=0;t<2;t++)
    #pragma unroll
    for (int u=0;u<4;u++)
      #pragma unroll
      for (int r=0;r<4;r++) acc[t][u][r]=0.f;

  for (int kc=0; kc<NTOK; kc+=64){
    __syncthreads();
    #pragma unroll
    for (int it=0; it<2; it++){
      int r = sr + it*32;
      size_t go = (size_t)(i0+r)*NTOK + kc + sseg*8;
      uint32_t so = (uint32_t)(r*TRI_LDS + sseg*8)*2;
      cp16(sLhi + so, &gLh[go]);
      cp16(sLlo + so, &gLl[go]);
    }
    #pragma unroll
    for (int it=0; it<4; it++){
      int r = sr + it*32;
      size_t go = (size_t)(j0+r)*NTOK + kc + sseg*8;
      uint32_t so = (uint32_t)(r*TRI_LDS + sseg*8)*2;
      cp16(sRhi + so, &gRh[go]);
      cp16(sRlo + so, &gRl[go]);
    }
    cp_commit_wait();
    __syncthreads();

    #pragma unroll
    for (int ks=0; ks<4; ks++){
      int ko = ks*16;
      uint32_t ah[2][4], al[2][4];
      #pragma unroll
      for (int t=0;t<2;t++){
        int row = wm*32 + t*16 + gid;
        int base = row*TRI_LDS + ko + 2*tig;
        ah[t][0] = *reinterpret_cast<const uint32_t*>(&Lhi[base]);
        ah[t][1] = *reinterpret_cast<const uint32_t*>(&Lhi[base + 8*TRI_LDS]);
        ah[t][2] = *reinterpret_cast<const uint32_t*>(&Lhi[base + 8]);
        ah[t][3] = *reinterpret_cast<const uint32_t*>(&Lhi[base + 8*TRI_LDS + 8]);
        al[t][0] = *reinterpret_cast<const uint32_t*>(&Llo[base]);
        al[t][1] = *reinterpret_cast<const uint32_t*>(&Llo[base + 8*TRI_LDS]);
        al[t][2] = *reinterpret_cast<const uint32_t*>(&Llo[base + 8]);
        al[t][3] = *reinterpret_cast<const uint32_t*>(&Llo[base + 8*TRI_LDS + 8]);
      }
      #pragma unroll
      for (int u=0;u<4;u++){
        int jrow = wn*32 + u*8 + gid;
        int bb = jrow*TRI_LDS + ko + 2*tig;
        uint32_t bh0 = *reinterpret_cast<const uint32_t*>(&Rhi[bb]);
        uint32_t bh1 = *reinterpret_cast<const uint32_t*>(&Rhi[bb + 8]);
        uint32_t bl0 = *reinterpret_cast<const uint32_t*>(&Rlo[bb]);
        uint32_t bl1 = *reinterpret_cast<const uint32_t*>(&Rlo[bb + 8]);
        #pragma unroll
        for (int t=0;t<2;t++){
          mma_bf16(acc[t][u], ah[t], bh0, bh1);
          mma_bf16(acc[t][u], ah[t], bl0, bl1);
          mma_bf16(acc[t][u], al[t], bh0, bh1);
        }
      }
    }
  }

  float* To = g_tri + (size_t)c*NROWS;
  #pragma unroll
  for (int t=0;t<2;t++){
    int iA = i0 + wm*32 + t*16 + gid;
    int iB = iA + 8;
    #pragma unroll
    for (int u=0;u<4;u++){
      int j = j0 + wn*32 + u*8 + 2*tig;
      float2 vA = {acc[t][u][0], acc[t][u][1]};
      float2 vB = {acc[t][u][2], acc[t][u][3]};
      *reinterpret_cast<float2*>(&To[(size_t)iA*NTOK + j]) = vA;
      *reinterpret_cast<float2*>(&To[(size_t)iB*NTOK + j]) = vB;
    }
  }
}

// ============== Stage 4: LN(tri) @ Wo + bo, * gate (tf32 mma) ==============
#define LDT 129
#define FINAL_SMEM ((128*LDT + XS_WORDS + W_WORDS)*4)
__global__ __launch_bounds__(512) void final_kernel(const float* __restrict__ cg,
                                                    const float* __restrict__ cb,
                                                    const float* __restrict__ Wo,
                                                    const float* __restrict__ bo,
                                                    float* __restrict__ out){
  extern __shared__ uint32_t sm[];
  float*    T  = reinterpret_cast<float*>(sm);
  uint32_t* xs = sm + 128*LDT;
  uint32_t* w  = xs + XS_WORDS;
  __shared__ float p1[4][128], p2[4][128], mu_s[128], rs_s[128];
  int tid  = threadIdx.x;
  int row0 = blockIdx.x * 128;

  #pragma unroll
  for (int it=0; it<8; ++it){
    int slot = tid + it*512;
    int cch = slot >> 5;
    int v4  = slot & 31;
    float4 v = *reinterpret_cast<const float4*>(&g_tri[(size_t)cch*NROWS + row0 + v4*4]);
    T[cch*LDT + v4*4 + 0] = v.x;
    T[cch*LDT + v4*4 + 1] = v.y;
    T[cch*LDT + v4*4 + 2] = v.z;
    T[cch*LDT + v4*4 + 3] = v.w;
    v = *reinterpret_cast<const float4*>(&Wo[cch*CDIM + v4*4]);
    uint4 t; t.x=tf32_rna(v.x); t.y=tf32_rna(v.y); t.z=tf32_rna(v.z); t.w=tf32_rna(v.w);
    *reinterpret_cast<uint4*>(&w[cch*LDW + v4*4]) = t;
  }
  __syncthreads();

  {
    int ij = tid & 127, pp = tid >> 7;
    float s=0.f, s2=0.f;
    #pragma unroll
    for (int k=0;k<32;k++){
      float v = T[(pp*32+k)*LDT + ij];
      s += v; s2 += v*v;
    }
    p1[pp][ij] = s; p2[pp][ij] = s2;
  }
  __syncthreads();
  if (tid < 128){
    float s  = p1[0][tid]+p1[1][tid]+p1[2][tid]+p1[3][tid];
    float s2 = p2[0][tid]+p2[1][tid]+p2[2][tid]+p2[3][tid];
    float mu = s*(1.f/128.f);
    mu_s[tid] = mu;
    rs_s[tid] = rsqrtf(s2*(1.f/128.f) - mu*mu + EPSV);
  }
  __syncthreads();

  #pragma unroll
  for (int it=0; it<8; ++it){
    int slot = tid + it*512;
    int r  = slot & 127;
    int cq = slot >> 7;
    float mu = mu_s[r], rs = rs_s[r];
    uint4 t;
    {
      int c0 = cq*4;
      float v0 = (T[(c0+0)*LDT + r]-mu)*rs*cg[c0+0] + cb[c0+0];
      float v1 = (T[(c0+1)*LDT + r]-mu)*rs*cg[c0+1] + cb[c0+1];
      float v2 = (T[(c0+2)*LDT + r]-mu)*rs*cg[c0+2] + cb[c0+2];
      float v3 = (T[(c0+3)*LDT + r]-mu)*rs*cg[c0+3] + cb[c0+3];
      t.x=tf32_rna(v0); t.y=tf32_rna(v1); t.z=tf32_rna(v2); t.w=tf32_rna(v3);
    }
    *reinterpret_cast<uint4*>(&xs[r*LDX + cq*4]) = t;
  }
  __syncthreads();

  int lane = tid&31, wid = tid>>5;
  int wm = wid>>2, wn = wid&3;
  int gid = lane>>2, tig = lane&3;

  float acc[2][4][4], accd[2][4][4];
  #pragma unroll
  for (int t=0;t<2;t++)
    #pragma unroll
    for (int u=0;u<4;u++)
      #pragma unroll
      for (int r=0;r<4;r++) acc[t][u][r]=0.f;

  gemm_pair(xs, w, w, wm, wn, gid, tig, acc, accd, false);

  #pragma unroll
  for (int t=0;t<2;t++){
    int rowA = row0 + wm*32 + t*16 + gid;
    int rowB = rowA + 8;
    #pragma unroll
    for (int u=0;u<4;u++){
      int colb = wn*32 + u*8 + 2*tig;
      float bo0 = bo[colb], bo1 = bo[colb+1];
      float2 gA = *reinterpret_cast<const float2*>(&g_gate[(size_t)rowA*CDIM + colb]);
      float2 gB = *reinterpret_cast<const float2*>(&g_gate[(size_t)rowB*CDIM + colb]);
      float2 oA, oB;
      oA.x = (acc[t][u][0]+bo0)*gA.x;
      oA.y = (acc[t][u][1]+bo1)*gA.y;
      oB.x = (acc[t][u][2]+bo0)*gB.x;
      oB.y = (acc[t][u][3]+bo1)*gB.y;
      *reinterpret_cast<float2*>(&out[(size_t)rowA*CDIM + colb]) = oA;
      *reinterpret_cast<float2*>(&out[(size_t)rowB*CDIM + colb]) = oB;
    }
  }
}

extern "C" void kernel_launch(void* const* d_in, const int* in_sizes, int n_in,
                              void* d_out, int out_size) {
  const float* act  = (const float*)d_in[0];
  const float* mask = (const float*)d_in[1];
  const float* ln_g = (const float*)d_in[2];
  const float* ln_b = (const float*)d_in[3];
  const float* Wl   = (const float*)d_in[4];
  const float* bl   = (const float*)d_in[5];
  const float* Wr   = (const float*)d_in[6];
  const float* br   = (const float*)d_in[7];
  const float* Wgl  = (const float*)d_in[8];
  const float* bgl  = (const float*)d_in[9];
  const float* Wgr  = (const float*)d_in[10];
  const float* bgr  = (const float*)d_in[11];
  const float* cg   = (const float*)d_in[12];
  const float* cb   = (const float*)d_in[13];
  const float* Wo   = (const float*)d_in[14];
  const float* bo   = (const float*)d_in[15];
  const float* Wg   = (const float*)d_in[16];
  const float* bg   = (const float*)d_in[17];
  float* out = (float*)d_out;

  __nv_bfloat16 *dLh=nullptr, *dLl=nullptr, *dRh=nullptr, *dRl=nullptr;
  float *dGate=nullptr;
  cudaGetSymbolAddress((void**)&dLh, g_Lhi);
  cudaGetSymbolAddress((void**)&dLl, g_Llo);
  cudaGetSymbolAddress((void**)&dRh, g_Rhi);
  cudaGetSymbolAddress((void**)&dRl, g_Rlo);
  cudaGetSymbolAddress((void**)&dGate, g_gate);

  cudaFuncSetAttribute(proj_all_kernel, cudaFuncAttributeMaxDynamicSharedMemorySize, PROJALL_SMEM);
  cudaFuncSetAttribute(tri_kernel,      cudaFuncAttributeMaxDynamicSharedMemorySize, TRI_SMEM);
  cudaFuncSetAttribute(final_kernel,    cudaFuncAttributeMaxDynamicSharedMemorySize, FINAL_SMEM);

  proj_all_kernel<<<NROWS/128, 512, PROJALL_SMEM>>>(act, ln_g, ln_b, mask,
      Wl, bl, Wgl, bgl, Wr, br, Wgr, bgr, Wg, bg,
      dLh, dLl, dRh, dRl, dGate);
  tri_kernel<<<dim3(NTOK/64, NTOK/128, CDIM), 256, TRI_SMEM>>>();
  final_kernel<<<NROWS/128, 512, FINAL_SMEM>>>(cg, cb, Wo, bo, out);
}

// round 13
// speedup vs baseline: 1.0802x; 1.0114x over previous
#include <cuda_runtime.h>
#include <cuda_bf16.h>
#include <cstdint>
#include <math.h>

#define NTOK 384
#define CDIM 128
#define NROWS (NTOK*NTOK)   /* 147456 */
#define EPSV 1e-5f

// Scratch (no cudaMalloc allowed)
__device__ float g_gate[(size_t)NROWS*CDIM];
__device__ float g_tri [(size_t)NROWS*CDIM];           // [c][i*384+j]
__device__ __nv_bfloat16 g_Lhi[(size_t)CDIM*NROWS];    // [c][i*384+k]
__device__ __nv_bfloat16 g_Llo[(size_t)CDIM*NROWS];
__device__ __nv_bfloat16 g_Rhi[(size_t)CDIM*NROWS];    // [c][j*384+k]
__device__ __nv_bfloat16 g_Rlo[(size_t)CDIM*NROWS];

// fast sigmoid: MUFU.EX2 + MUFU.RCP path (rel err ~2^-21, tolerance is 1e-3)
__device__ __forceinline__ float fsig(float z){
  return __fdividef(1.f, 1.f + __expf(-z));
}

__device__ __forceinline__ uint32_t tf32_rna(float f){
  uint32_t r; asm("cvt.rna.tf32.f32 %0, %1;" : "=r"(r) : "f"(f)); return r;
}
__device__ __forceinline__ uint32_t prmt_(uint32_t a, uint32_t b, uint32_t s){
  uint32_t d; asm("prmt.b32 %0,%1,%2,%3;" : "=r"(d) : "r"(a), "r"(b), "r"(s)); return d;
}
__device__ __forceinline__ uint32_t pack_hilo(float v){
  __nv_bfloat16 h = __float2bfloat16(v);
  float rem = v - __bfloat162float(h);
  __nv_bfloat16 l = __float2bfloat16(rem);
  uint16_t hb = *reinterpret_cast<uint16_t*>(&h);
  uint16_t lb = *reinterpret_cast<uint16_t*>(&l);
  return (uint32_t)hb | ((uint32_t)lb << 16);
}
__device__ __forceinline__ uint32_t smem_u32(const void* p){
  uint32_t a;
  asm("{ .reg .u64 t; cvta.to.shared.u64 t, %1; cvt.u32.u64 %0, t; }" : "=r"(a) : "l"(p));
  return a;
}
__device__ __forceinline__ void cp16(uint32_t dst_smem, const void* src){
  asm volatile("cp.async.ca.shared.global [%0], [%1], 16;" :: "r"(dst_smem), "l"(src));
}
__device__ __forceinline__ void cp_commit_wait(){
  asm volatile("cp.async.commit_group;");
  asm volatile("cp.async.wait_group 0;");
}
// ldmatrix x4 (sm_75 base ISA)
__device__ __forceinline__ void ldm4(uint32_t* r, uint32_t addr){
  asm volatile("ldmatrix.sync.aligned.m8n8.x4.shared.b16 {%0,%1,%2,%3}, [%4];"
    : "=r"(r[0]), "=r"(r[1]), "=r"(r[2]), "=r"(r[3]) : "r"(addr));
}

// m16n8k8 tf32 mma (sm_80 base ISA)
__device__ __forceinline__ void mma_tf32(float& d0, float& d1, float& d2, float& d3,
                                         uint32_t a0, uint32_t a1, uint32_t a2, uint32_t a3,
                                         uint32_t b0, uint32_t b1){
  asm volatile(
    "mma.sync.aligned.m16n8k8.row.col.f32.tf32.tf32.f32 "
    "{%0,%1,%2,%3}, {%4,%5,%6,%7}, {%8,%9}, {%0,%1,%2,%3};"
    : "+f"(d0), "+f"(d1), "+f"(d2), "+f"(d3)
    : "r"(a0), "r"(a1), "r"(a2), "r"(a3), "r"(b0), "r"(b1));
}

// m16n8k16 bf16 mma (sm_80 base ISA)
__device__ __forceinline__ void mma_bf16(float* d, const uint32_t* a, uint32_t b0, uint32_t b1){
  asm volatile(
    "mma.sync.aligned.m16n8k16.row.col.f32.bf16.bf16.f32 "
    "{%0,%1,%2,%3}, {%4,%5,%6,%7}, {%8,%9}, {%0,%1,%2,%3};"
    : "+f"(d[0]), "+f"(d[1]), "+f"(d[2]), "+f"(d[3])
    : "r"(a[0]), "r"(a[1]), "r"(a[2]), "r"(a[3]), "r"(b0), "r"(b1));
}

// ================= fused LN + 5 projections =================
#define LDX 132
#define LDW 136
#define LDE 132
#define XS_WORDS (128*LDX)
#define W_WORDS  (128*LDW)
#define PROJALL_SMEM ((XS_WORDS + 2*W_WORDS)*4)

__device__ __forceinline__ void gemm_pair(const uint32_t* __restrict__ xs,
                                          const uint32_t* __restrict__ w1,
                                          const uint32_t* __restrict__ w2,
                                          int wm, int wn, int gid, int tig,
                                          float acc1[2][4][4], float acc2[2][4][4],
                                          bool dual){
  const uint32_t* xa  = xs + (wm*32 + gid)*LDX + tig;
  const uint32_t* wb1 = w1 + tig*LDW + wn*32 + gid;
  const uint32_t* wb2 = w2 + tig*LDW + wn*32 + gid;
  #pragma unroll
  for (int kc=0; kc<16; kc++){
    uint32_t a[2][4];
    #pragma unroll
    for (int t=0;t<2;t++){
      const uint32_t* p = xa + t*16*LDX + kc*8;
      a[t][0] = p[0];
      a[t][1] = p[8*LDX];
      a[t][2] = p[4];
      a[t][3] = p[8*LDX + 4];
    }
    #pragma unroll
    for (int u=0;u<4;u++){
      const uint32_t* q1 = wb1 + kc*8*LDW + u*8;
      uint32_t b10 = q1[0], b11 = q1[4*LDW];
      #pragma unroll
      for (int t=0;t<2;t++)
        mma_tf32(acc1[t][u][0],acc1[t][u][1],acc1[t][u][2],acc1[t][u][3],
                 a[t][0],a[t][1],a[t][2],a[t][3], b10,b11);
      if (dual){
        const uint32_t* q2 = wb2 + kc*8*LDW + u*8;
        uint32_t b20 = q2[0], b21 = q2[4*LDW];
        #pragma unroll
        for (int t=0;t<2;t++)
          mma_tf32(acc2[t][u][0],acc2[t][u][1],acc2[t][u][2],acc2[t][u][3],
                   a[t][0],a[t][1],a[t][2],a[t][3], b20,b21);
      }
    }
  }
}

__device__ __forceinline__ void ldgW(const float* __restrict__ W, int tid, uint4 w[8]){
  #pragma unroll
  for (int it=0; it<8; ++it){
    int slot = tid + it*512;
    int r  = slot >> 5;
    int kv = slot & 31;
    w[it] = *reinterpret_cast<const uint4*>(&W[r*CDIM + kv*4]);
  }
}
__device__ __forceinline__ void stsW(const uint4 w[8], int tid, uint32_t* __restrict__ dst){
  #pragma unroll
  for (int it=0; it<8; ++it){
    int slot = tid + it*512;
    int r  = slot >> 5;
    int kv = slot & 31;
    float4 v = *reinterpret_cast<const float4*>(&w[it]);
    uint4 t; t.x=tf32_rna(v.x); t.y=tf32_rna(v.y); t.z=tf32_rna(v.z); t.w=tf32_rna(v.w);
    *reinterpret_cast<uint4*>(&dst[r*LDW + kv*4]) = t;
  }
}

__device__ __forceinline__ void compute_pk(const float acc1[2][4][4], const float acc2[2][4][4],
    const float* __restrict__ mask, const float* __restrict__ bb1, const float* __restrict__ bb2,
    int row0, int wm, int wn, int gid, int tig, uint32_t pk[32]){
  #pragma unroll
  for (int t=0;t<2;t++){
    int rA = wm*32 + t*16 + gid;
    int rB = rA + 8;
    float mvA = mask[row0 + rA], mvB = mask[row0 + rB];
    #pragma unroll
    for (int u=0;u<4;u++){
      int colb = wn*32 + u*8 + 2*tig;
      float2 b1v = *reinterpret_cast<const float2*>(&bb1[colb]);
      float2 b2v = *reinterpret_cast<const float2*>(&bb2[colb]);
      float v0 = mvA*(acc1[t][u][0]+b1v.x)*fsig(acc2[t][u][0]+b2v.x);
      float v1 = mvA*(acc1[t][u][1]+b1v.y)*fsig(acc2[t][u][1]+b2v.y);
      float v2 = mvB*(acc1[t][u][2]+b1v.x)*fsig(acc2[t][u][2]+b2v.x);
      float v3 = mvB*(acc1[t][u][3]+b1v.y)*fsig(acc2[t][u][3]+b2v.y);
      pk[t*16+u*4+0] = pack_hilo(v0);
      pk[t*16+u*4+1] = pack_hilo(v1);
      pk[t*16+u*4+2] = pack_hilo(v2);
      pk[t*16+u*4+3] = pack_hilo(v3);
    }
  }
}

__device__ __forceinline__ void epi_store_1p(const uint32_t pk[32], uint32_t* __restrict__ ebuf,
    __nv_bfloat16* __restrict__ ghi, __nv_bfloat16* __restrict__ glo,
    int row0, int tid, int wm, int wn, int gid, int tig){
  #pragma unroll
  for (int t=0;t<2;t++){
    int rA = wm*32 + t*16 + gid;
    int rB = rA + 8;
    #pragma unroll
    for (int u=0;u<4;u++){
      int cl = wn*32 + u*8 + 2*tig;
      ebuf[ cl   *LDE + rA] = pk[t*16+u*4+0];
      ebuf[(cl+1)*LDE + rA] = pk[t*16+u*4+1];
      ebuf[ cl   *LDE + rB] = pk[t*16+u*4+2];
      ebuf[(cl+1)*LDE + rB] = pk[t*16+u*4+3];
    }
  }
  __syncthreads();
  {
    int rb = tid & 15;
    int cb = tid >> 4;
    #pragma unroll
    for (int p=0;p<4;p++){
      int cl = cb + 32*p;
      #pragma unroll
      for (int h=0; h<2; h++){
        int rq = rb + 16*h;
        uint4 w = *reinterpret_cast<const uint4*>(&ebuf[cl*LDE + rq*4]);
        uint32_t hi01 = prmt_(w.x, w.y, 0x5410u);
        uint32_t hi23 = prmt_(w.z, w.w, 0x5410u);
        uint32_t lo01 = prmt_(w.x, w.y, 0x7632u);
        uint32_t lo23 = prmt_(w.z, w.w, 0x7632u);
        size_t base = (size_t)cl*NROWS + row0 + rq*4;
        *reinterpret_cast<uint2*>(&ghi[base]) = make_uint2(hi01, hi23);
        *reinterpret_cast<uint2*>(&glo[base]) = make_uint2(lo01, lo23);
      }
    }
  }
  __syncthreads();
}

__global__ __launch_bounds__(512) void proj_all_kernel(
    const float* __restrict__ act, const float* __restrict__ lng, const float* __restrict__ lnb,
    const float* __restrict__ mask,
    const float* __restrict__ Wl,  const float* __restrict__ bl,
    const float* __restrict__ Wgl, const float* __restrict__ bgl,
    const float* __restrict__ Wr,  const float* __restrict__ br,
    const float* __restrict__ Wgr, const float* __restrict__ bgr,
    const float* __restrict__ Wg,  const float* __restrict__ bg,
    __nv_bfloat16* __restrict__ gLh, __nv_bfloat16* __restrict__ gLl,
    __nv_bfloat16* __restrict__ gRh, __nv_bfloat16* __restrict__ gRl,
    float* __restrict__ gate){
  extern __shared__ uint32_t sm[];
  uint32_t* xs   = sm;
  uint32_t* w1   = sm + XS_WORDS;
  uint32_t* w2   = w1 + W_WORDS;
  int tid  = threadIdx.x;
  int row0 = blockIdx.x * 128;
  int kv   = tid & 31;

  {
    uint4 va[8];
    #pragma unroll
    for (int it=0; it<8; ++it){
      int r = (tid>>5) + it*16;
      va[it] = *reinterpret_cast<const uint4*>(&act[(size_t)(row0+r)*CDIM + kv*4]);
    }
    uint4 wA[8], wB[8];
    ldgW(Wl,  tid, wA);
    ldgW(Wgl, tid, wB);
    float4 g4 = *reinterpret_cast<const float4*>(&lng[kv*4]);
    float4 b4 = *reinterpret_cast<const float4*>(&lnb[kv*4]);
    #pragma unroll
    for (int it=0; it<8; ++it){
      int r = (tid>>5) + it*16;
      float4 v = *reinterpret_cast<const float4*>(&va[it]);
      float s  = v.x + v.y + v.z + v.w;
      float s2 = v.x*v.x + v.y*v.y + v.z*v.z + v.w*v.w;
      #pragma unroll
      for (int off=16; off>0; off>>=1){
        s  += __shfl_xor_sync(0xffffffffu, s,  off);
        s2 += __shfl_xor_sync(0xffffffffu, s2, off);
      }
      float mu = s * (1.f/128.f);
      float rs = rsqrtf(s2*(1.f/128.f) - mu*mu + EPSV);
      uint4 t;
      t.x = tf32_rna((v.x-mu)*rs*g4.x + b4.x);
      t.y = tf32_rna((v.y-mu)*rs*g4.y + b4.y);
      t.z = tf32_rna((v.z-mu)*rs*g4.z + b4.z);
      t.w = tf32_rna((v.w-mu)*rs*g4.w + b4.w);
      *reinterpret_cast<uint4*>(&xs[r*LDX + kv*4]) = t;
    }
    stsW(wA, tid, w1);
    stsW(wB, tid, w2);
  }
  __syncthreads();

  int lane = tid&31, wid = tid>>5;
  int wm = wid>>2, wn = wid&3;
  int gid = lane>>2, tig = lane&3;

  float acc1[2][4][4], acc2[2][4][4];
  uint32_t pk[32];

  // ---- GEMM 1: left (dual) ----
  #pragma unroll
  for (int t=0;t<2;t++)
    #pragma unroll
    for (int u=0;u<4;u++)
      #pragma unroll
      for (int r=0;r<4;r++){ acc1[t][u][r]=0.f; acc2[t][u][r]=0.f; }
  gemm_pair(xs, w1, w2, wm, wn, gid, tig, acc1, acc2, true);
  compute_pk(acc1, acc2, mask, bl, bgl, row0, wm, wn, gid, tig, pk);
  __syncthreads();
  {
    uint4 wA[8], wB[8];
    ldgW(Wr,  tid, wA);
    ldgW(Wgr, tid, wB);
    epi_store_1p(pk, w1, gLh, gLl, row0, tid, wm, wn, gid, tig);
    stsW(wA, tid, w1);
    stsW(wB, tid, w2);
  }
  __syncthreads();

  // ---- GEMM 2: right (dual) ----
  #pragma unroll
  for (int t=0;t<2;t++)
    #pragma unroll
    for (int u=0;u<4;u++)
      #pragma unroll
      for (int r=0;r<4;r++){ acc1[t][u][r]=0.f; acc2[t][u][r]=0.f; }
  gemm_pair(xs, w1, w2, wm, wn, gid, tig, acc1, acc2, true);
  compute_pk(acc1, acc2, mask, br, bgr, row0, wm, wn, gid, tig, pk);
  __syncthreads();
  {
    uint4 wA[8];
    ldgW(Wg, tid, wA);
    epi_store_1p(pk, w1, gRh, gRl, row0, tid, wm, wn, gid, tig);
    stsW(wA, tid, w1);
  }
  __syncthreads();

  // ---- GEMM 3: gate (single) ----
  #pragma unroll
  for (int t=0;t<2;t++)
    #pragma unroll
    for (int u=0;u<4;u++)
      #pragma unroll
      for (int r=0;r<4;r++) acc1[t][u][r]=0.f;
  gemm_pair(xs, w1, w1, wm, wn, gid, tig, acc1, acc2, false);
  #pragma unroll
  for (int t=0;t<2;t++){
    int rowA = row0 + wm*32 + t*16 + gid;
    int rowB = rowA + 8;
    #pragma unroll
    for (int u=0;u<4;u++){
      int colb = wn*32 + u*8 + 2*tig;
      float b0 = bg[colb], b1 = bg[colb+1];
      float2 oA, oB;
      oA.x = fsig(acc1[t][u][0]+b0);
      oA.y = fsig(acc1[t][u][1]+b1);
      oB.x = fsig(acc1[t][u][2]+b0);
      oB.y = fsig(acc1[t][u][3]+b1);
      *reinterpret_cast<float2*>(&gate[(size_t)rowA*CDIM + colb]) = oA;
      *reinterpret_cast<float2*>(&gate[(size_t)rowB*CDIM + colb]) = oB;
    }
  }
}

// ============== Stage 3: per-channel GEMM via bf16-split mma + ldmatrix ==============
// cp.async staging; 64x128 tile; 2 CTAs/SM; fragment loads via ldmatrix.x4 (8 per ks vs 64 LDS).
#define TRI_LDS 72
#define TRI_SMEM ((64*TRI_LDS*2 + 128*TRI_LDS*2)*2)
__global__ __launch_bounds__(256, 2) void tri_kernel(){
  extern __shared__ __nv_bfloat16 smb[];
  __nv_bfloat16* Lhi = smb;
  __nv_bfloat16* Llo = smb + 64*TRI_LDS;
  __nv_bfloat16* Rhi = smb + 2*64*TRI_LDS;
  __nv_bfloat16* Rlo = Rhi + 128*TRI_LDS;
  uint32_t sLhi = smem_u32(Lhi);
  uint32_t sLlo = smem_u32(Llo);
  uint32_t sRhi = smem_u32(Rhi);
  uint32_t sRlo = smem_u32(Rlo);
  int tid = threadIdx.x;
  int c  = blockIdx.z;
  int i0 = blockIdx.x * 64;
  int j0 = blockIdx.y * 128;
  const __nv_bfloat16* gLh = g_Lhi + (size_t)c*NROWS;
  const __nv_bfloat16* gLl = g_Llo + (size_t)c*NROWS;
  const __nv_bfloat16* gRh = g_Rhi + (size_t)c*NROWS;
  const __nv_bfloat16* gRl = g_Rlo + (size_t)c*NROWS;

  int lane = tid&31, wid = tid>>5;
  int wm = wid>>2, wn = wid&3;
  int gid = lane>>2, tig = lane&3;

  int sr = tid>>3, sseg = tid&7;

  // ldmatrix per-lane byte offsets (within a buffer), loop-invariant except ks
  // A (16x16 tile at row0_t): row = base + (lane&15), col = ks*16 + ((lane>>4)<<3)
  uint32_t offA0 = (uint32_t)(((wm*32 + (lane&15))*TRI_LDS + ((lane>>4)<<3))*2);
  uint32_t offA1 = offA0 + (uint32_t)(16*TRI_LDS*2);
  // B (two n8k16 tiles, u-pair): row = base + (lane&7) + ((lane>>4)<<3), col = ks*16 + (((lane>>3)&1)<<3)
  uint32_t offB0 = (uint32_t)(((wn*32 + (lane&7) + ((lane>>4)<<3))*TRI_LDS + (((lane>>3)&1)<<3))*2);
  uint32_t offB2 = offB0 + (uint32_t)(16*TRI_LDS*2);

  float acc[2][4][4];
  #pragma unroll
  for (int t=0;t<2;t++)
    #pragma unroll
    for (int u=0;u<4;u++)
      #pragma unroll
      for (int r=0;r<4;r++) acc[t][u][r]=0.f;

  for (int kc=0; kc<NTOK; kc+=64){
    __syncthreads();
    #pragma unroll
    for (int it=0; it<2; it++){
      int r = sr + it*32;
      size_t go = (size_t)(i0+r)*NTOK + kc + sseg*8;
      uint32_t so = (uint32_t)(r*TRI_LDS + sseg*8)*2;
      cp16(sLhi + so, &gLh[go]);
      cp16(sLlo + so, &gLl[go]);
    }
    #pragma unroll
    for (int it=0; it<4; it++){
      int r = sr + it*32;
      size_t go = (size_t)(j0+r)*NTOK + kc + sseg*8;
      uint32_t so = (uint32_t)(r*TRI_LDS + sseg*8)*2;
      cp16(sRhi + so, &gRh[go]);
      cp16(sRlo + so, &gRl[go]);
    }
    cp_commit_wait();
    __syncthreads();

    #pragma unroll
    for (int ks=0; ks<4; ks++){
      uint32_t kso = (uint32_t)(ks*32);   // 16 bf16 = 32 bytes per k-step
      uint32_t ah[2][4], al[2][4];
      ldm4(ah[0], sLhi + offA0 + kso);
      ldm4(ah[1], sLhi + offA1 + kso);
      ldm4(al[0], sLlo + offA0 + kso);
      ldm4(al[1], sLlo + offA1 + kso);
      uint32_t bh01[4], bh23[4], bl01[4], bl23[4];
      ldm4(bh01, sRhi + offB0 + kso);
      ldm4(bh23, sRhi + offB2 + kso);
      ldm4(bl01, sRhi==0 ? 0 : (sRlo + offB0 + kso));   // (sRlo path)
      ldm4(bl23, sRlo + offB2 + kso);
      // u = 0..3: b regs (b0,b1) = (bh01[0],bh01[1]) u0; (bh01[2],bh01[3]) u1; bh23 for u2,u3
      const uint32_t* bhp[4] = { &bh01[0], &bh01[2], &bh23[0], &bh23[2] };
      const uint32_t* blp[4] = { &bl01[0], &bl01[2], &bl23[0], &bl23[2] };
      #pragma unroll
      for (int u=0;u<4;u++){
        uint32_t bh0 = bhp[u][0], bh1 = bhp[u][1];
        uint32_t bl0 = blp[u][0], bl1 = blp[u][1];
        #pragma unroll
        for (int t=0;t<2;t++){
          mma_bf16(acc[t][u], ah[t], bh0, bh1);
          mma_bf16(acc[t][u], ah[t], bl0, bl1);
          mma_bf16(acc[t][u], al[t], bh0, bh1);
        }
      }
    }
  }

  float* To = g_tri + (size_t)c*NROWS;
  #pragma unroll
  for (int t=0;t<2;t++){
    int iA = i0 + wm*32 + t*16 + gid;
    int iB = iA + 8;
    #pragma unroll
    for (int u=0;u<4;u++){
      int j = j0 + wn*32 + u*8 + 2*tig;
      float2 vA = {acc[t][u][0], acc[t][u][1]};
      float2 vB = {acc[t][u][2], acc[t][u][3]};
      *reinterpret_cast<float2*>(&To[(size_t)iA*NTOK + j]) = vA;
      *reinterpret_cast<float2*>(&To[(size_t)iB*NTOK + j]) = vB;
    }
  }
}

// ============== Stage 4: LN(tri) @ Wo + bo, * gate (tf32 mma) ==============
#define LDT 129
#define FINAL_SMEM ((128*LDT + XS_WORDS + W_WORDS)*4)
__global__ __launch_bounds__(512) void final_kernel(const float* __restrict__ cg,
                                                    const float* __restrict__ cb,
                                                    const float* __restrict__ Wo,
                                                    const float* __restrict__ bo,
                                                    float* __restrict__ out){
  extern __shared__ uint32_t sm[];
  float*    T  = reinterpret_cast<float*>(sm);
  uint32_t* xs = sm + 128*LDT;
  uint32_t* w  = xs + XS_WORDS;
  __shared__ float p1[4][128], p2[4][128], mu_s[128], rs_s[128];
  int tid  = threadIdx.x;
  int row0 = blockIdx.x * 128;

  #pragma unroll
  for (int it=0; it<8; ++it){
    int slot = tid + it*512;
    int cch = slot >> 5;
    int v4  = slot & 31;
    float4 v = *reinterpret_cast<const float4*>(&g_tri[(size_t)cch*NROWS + row0 + v4*4]);
    T[cch*LDT + v4*4 + 0] = v.x;
    T[cch*LDT + v4*4 + 1] = v.y;
    T[cch*LDT + v4*4 + 2] = v.z;
    T[cch*LDT + v4*4 + 3] = v.w;
    v = *reinterpret_cast<const float4*>(&Wo[cch*CDIM + v4*4]);
    uint4 t; t.x=tf32_rna(v.x); t.y=tf32_rna(v.y); t.z=tf32_rna(v.z); t.w=tf32_rna(v.w);
    *reinterpret_cast<uint4*>(&w[cch*LDW + v4*4]) = t;
  }
  __syncthreads();

  {
    int ij = tid & 127, pp = tid >> 7;
    float s=0.f, s2=0.f;
    #pragma unroll
    for (int k=0;k<32;k++){
      float v = T[(pp*32+k)*LDT + ij];
      s += v; s2 += v*v;
    }
    p1[pp][ij] = s; p2[pp][ij] = s2;
  }
  __syncthreads();
  if (tid < 128){
    float s  = p1[0][tid]+p1[1][tid]+p1[2][tid]+p1[3][tid];
    float s2 = p2[0][tid]+p2[1][tid]+p2[2][tid]+p2[3][tid];
    float mu = s*(1.f/128.f);
    mu_s[tid] = mu;
    rs_s[tid] = rsqrtf(s2*(1.f/128.f) - mu*mu + EPSV);
  }
  __syncthreads();

  #pragma unroll
  for (int it=0; it<8; ++it){
    int slot = tid + it*512;
    int r  = slot & 127;
    int cq = slot >> 7;
    float mu = mu_s[r], rs = rs_s[r];
    uint4 t;
    {
      int c0 = cq*4;
      float v0 = (T[(c0+0)*LDT + r]-mu)*rs*cg[c0+0] + cb[c0+0];
      float v1 = (T[(c0+1)*LDT + r]-mu)*rs*cg[c0+1] + cb[c0+1];
      float v2 = (T[(c0+2)*LDT + r]-mu)*rs*cg[c0+2] + cb[c0+2];
      float v3 = (T[(c0+3)*LDT + r]-mu)*rs*cg[c0+3] + cb[c0+3];
      t.x=tf32_rna(v0); t.y=tf32_rna(v1); t.z=tf32_rna(v2); t.w=tf32_rna(v3);
    }
    *reinterpret_cast<uint4*>(&xs[r*LDX + cq*4]) = t;
  }
  __syncthreads();

  int lane = tid&31, wid = tid>>5;
  int wm = wid>>2, wn = wid&3;
  int gid = lane>>2, tig = lane&3;

  float acc[2][4][4], accd[2][4][4];
  #pragma unroll
  for (int t=0;t<2;t++)
    #pragma unroll
    for (int u=0;u<4;u++)
      #pragma unroll
      for (int r=0;r<4;r++) acc[t][u][r]=0.f;

  gemm_pair(xs, w, w, wm, wn, gid, tig, acc, accd, false);

  #pragma unroll
  for (int t=0;t<2;t++){
    int rowA = row0 + wm*32 + t*16 + gid;
    int rowB = rowA + 8;
    #pragma unroll
    for (int u=0;u<4;u++){
      int colb = wn*32 + u*8 + 2*tig;
      float bo0 = bo[colb], bo1 = bo[colb+1];
      float2 gA = *reinterpret_cast<const float2*>(&g_gate[(size_t)rowA*CDIM + colb]);
      float2 gB = *reinterpret_cast<const float2*>(&g_gate[(size_t)rowB*CDIM + colb]);
      float2 oA, oB;
      oA.x = (acc[t][u][0]+bo0)*gA.x;
      oA.y = (acc[t][u][1]+bo1)*gA.y;
      oB.x = (acc[t][u][2]+bo0)*gB.x;
      oB.y = (acc[t][u][3]+bo1)*gB.y;
      *reinterpret_cast<float2*>(&out[(size_t)rowA*CDIM + colb]) = oA;
      *reinterpret_cast<float2*>(&out[(size_t)rowB*CDIM + colb]) = oB;
    }
  }
}

extern "C" void kernel_launch(void* const* d_in, const int* in_sizes, int n_in,
                              void* d_out, int out_size) {
  const float* act  = (const float*)d_in[0];
  const float* mask = (const float*)d_in[1];
  const float* ln_g = (const float*)d_in[2];
  const float* ln_b = (const float*)d_in[3];
  const float* Wl   = (const float*)d_in[4];
  const float* bl   = (const float*)d_in[5];
  const float* Wr   = (const float*)d_in[6];
  const float* br   = (const float*)d_in[7];
  const float* Wgl  = (const float*)d_in[8];
  const float* bgl  = (const float*)d_in[9];
  const float* Wgr  = (const float*)d_in[10];
  const float* bgr  = (const float*)d_in[11];
  const float* cg   = (const float*)d_in[12];
  const float* cb   = (const float*)d_in[13];
  const float* Wo   = (const float*)d_in[14];
  const float* bo   = (const float*)d_in[15];
  const float* Wg   = (const float*)d_in[16];
  const float* bg   = (const float*)d_in[17];
  float* out = (float*)d_out;

  __nv_bfloat16 *dLh=nullptr, *dLl=nullptr, *dRh=nullptr, *dRl=nullptr;
  float *dGate=nullptr;
  cudaGetSymbolAddress((void**)&dLh, g_Lhi);
  cudaGetSymbolAddress((void**)&dLl, g_Llo);
  cudaGetSymbolAddress((void**)&dRh, g_Rhi);
  cudaGetSymbolAddress((void**)&dRl, g_Rlo);
  cudaGetSymbolAddress((void**)&dGate, g_gate);

  cudaFuncSetAttribute(proj_all_kernel, cudaFuncAttributeMaxDynamicSharedMemorySize, PROJALL_SMEM);
  cudaFuncSetAttribute(tri_kernel,      cudaFuncAttributeMaxDynamicSharedMemorySize, TRI_SMEM);
  cudaFuncSetAttribute(final_kernel,    cudaFuncAttributeMaxDynamicSharedMemorySize, FINAL_SMEM);

  proj_all_kernel<<<NROWS/128, 512, PROJALL_SMEM>>>(act, ln_g, ln_b, mask,
      Wl, bl, Wgl, bgl, Wr, br, Wgr, bgr, Wg, bg,
      dLh, dLl, dRh, dRl, dGate);
  tri_kernel<<<dim3(NTOK/64, NTOK/128, CDIM), 256, TRI_SMEM>>>();
  final_kernel<<<NROWS/128, 512, FINAL_SMEM>>>(cg, cb, Wo, bo, out);
}